// round 10
// baseline (speedup 1.0000x reference)
#include <cuda_runtime.h>
#include <cuda_fp16.h>
#include <math.h>
#include <stddef.h>
#include <stdint.h>

#define Bb   32
#define Hh   56
#define Ww   56
#define Cc   192
#define WS   7
#define SS   3
#define NHd  6
#define Nn   49
#define HD   32
#define NWTOT 2048
#define TOK  100352
#define HID  768
#define SCALE 0.17677669529663687f  /* 32^-0.5 */

// ---------------- scratch (device globals; no allocations) ----------------
__device__ __half g_xw16  [(size_t)TOK * Cc];
__device__ __half g_qkv16 [(size_t)TOK * 3 * Cc];
__device__ __half g_attn16[(size_t)TOK * Cc];
__device__ float  g_h     [(size_t)TOK * Cc];
__device__ __half g_ln216 [(size_t)TOK * Cc];
__device__ __half g_act16 [(size_t)TOK * HID];
__device__ __half g_qkvw16[3 * Cc * Cc];
__device__ __half g_projw16[Cc * Cc];
__device__ __half g_fc1w16[HID * Cc];
__device__ __half g_fc2w16[Cc * HID];
__device__ float  g_tab   [24 * 64 * 64];     // (cls*6+nh) x 64 x 64 bias+mask

// ---------------- helpers ----------------
static __device__ __forceinline__ uint32_t smem_u32(const void* p) {
    uint32_t a;
    asm("{ .reg .u64 t; cvta.to.shared.u64 t, %1; cvt.u32.u64 %0, t; }" : "=r"(a) : "l"(p));
    return a;
}
static __device__ __forceinline__ void ldsm4(uint32_t& r0, uint32_t& r1, uint32_t& r2,
                                             uint32_t& r3, uint32_t addr) {
    asm volatile("ldmatrix.sync.aligned.m8n8.x4.shared.b16 {%0,%1,%2,%3}, [%4];"
                 : "=r"(r0), "=r"(r1), "=r"(r2), "=r"(r3) : "r"(addr));
}
static __device__ __forceinline__ void mma_f16(float* c, const uint32_t* a, const uint32_t* b) {
    asm volatile(
        "mma.sync.aligned.m16n8k16.row.col.f32.f16.f16.f32 "
        "{%0,%1,%2,%3}, {%4,%5,%6,%7}, {%8,%9}, {%0,%1,%2,%3};"
        : "+f"(c[0]), "+f"(c[1]), "+f"(c[2]), "+f"(c[3])
        : "r"(a[0]), "r"(a[1]), "r"(a[2]), "r"(a[3]), "r"(b[0]), "r"(b[1]));
}
static __device__ __forceinline__ void cpa16(uint32_t dst, const void* src) {
    asm volatile("cp.async.ca.shared.global [%0], [%1], 16;" :: "r"(dst), "l"(src));
}
static __device__ __forceinline__ uint32_t h2u(float a, float b) {
    __half2 h = __floats2half2_rn(a, b);
    return *(uint32_t*)&h;
}
#define DIV7(u) (((u) * 9363) >> 16)

static __device__ __forceinline__ float wsum(float v) {
    #pragma unroll
    for (int o = 16; o; o >>= 1) v += __shfl_xor_sync(0xffffffffu, v, o);
    return v;
}

// ---------------- fused weight conversion ----------------
__global__ void cvt_all(const float* __restrict__ qkvw, const float* __restrict__ projw,
                        const float* __restrict__ fc1w, const float* __restrict__ fc2w) {
    int i = blockIdx.x * 256 + threadIdx.x;
    const int S0 = 3 * Cc * Cc, S1 = Cc * Cc, S2 = HID * Cc, S3 = Cc * HID;
    if (i < S0) { g_qkvw16[i] = __float2half(qkvw[i]); return; }
    i -= S0;
    if (i < S1) { g_projw16[i] = __float2half(projw[i]); return; }
    i -= S1;
    if (i < S2) { g_fc1w16[i] = __float2half(fc1w[i]); return; }
    i -= S2;
    if (i < S3) { g_fc2w16[i] = __float2half(fc2w[i]); }
}

// ---------------- bias+mask tables: 4 window classes x 6 heads x 64x64 ----------------
__global__ void build_tab(const float* __restrict__ rpb) {
    int cls = blockIdx.x / NHd, nh = blockIdx.x - cls * NHd;
    int lastR = (cls >> 1) & 1, lastC = cls & 1;
    float* tp = g_tab + blockIdx.x * 4096;
    for (int idx = threadIdx.x; idx < 4096; idx += 256) {
        int rI = idx >> 6, m = idx & 63;
        float v;
        if (rI >= Nn) v = 0.0f;
        else if (m >= Nn) v = -1e30f;
        else {
            int r1 = DIV7(rI), c1 = rI - r1 * 7;
            int r2 = DIV7(m),  c2 = m  - r2 * 7;
            float bias = rpb[((r1 - r2 + 6) * 13 + (c1 - c2 + 6)) * NHd + nh];
            int rg1 = (lastR ? (r1 < 4 ? 1 : 2) : 0) * 3 + (lastC ? (c1 < 4 ? 1 : 2) : 0);
            int rg2 = (lastR ? (r2 < 4 ? 1 : 2) : 0) * 3 + (lastC ? (c2 < 4 ? 1 : 2) : 0);
            v = bias + ((rg1 == rg2) ? 0.0f : -100.0f);
        }
        tp[idx] = v;
    }
}

// ---------------- LN1 + roll(-3,-3) + window partition (warp per token) ----------------
__global__ void __launch_bounds__(256)
ln1_shift_part(const float* __restrict__ x, const float* __restrict__ g,
               const float* __restrict__ b) {
    int t = blockIdx.x * 8 + (threadIdx.x >> 5);
    int lane = threadIdx.x & 31;
    int wi = t / Nn, n = t - wi * Nn;
    int bi = wi >> 6, wl = wi & 63;
    int wr = wl >> 3, wc = wl & 7;
    int r = DIV7(n), c2 = n - r * 7;
    int hsrc = (wr * 7 + r + SS) % Hh;
    int wsrc = (wc * 7 + c2 + SS) % Ww;
    const float* row = x + ((size_t)bi * (Hh * Ww) + hsrc * Ww + wsrc) * Cc;
    float v[6];
    float s = 0.0f;
    #pragma unroll
    for (int j = 0; j < 6; j++) { v[j] = row[lane + 32 * j]; s += v[j]; }
    float mean = wsum(s) * (1.0f / Cc);
    float q = 0.0f;
    #pragma unroll
    for (int j = 0; j < 6; j++) { v[j] -= mean; q += v[j] * v[j]; }
    float inv = rsqrtf(wsum(q) * (1.0f / Cc) + 1e-5f);
    __half* o = g_xw16 + (size_t)t * Cc;
    #pragma unroll
    for (int j = 0; j < 6; j++) {
        int c = lane + 32 * j;
        o[c] = __float2half(v[j] * inv * g[c] + b[c]);
    }
}

// ---------------- wide fp16 TC GEMM: BM=128, BN=192, BK=32; 192 thr (6 warps 2x3) ----------------
// EPI: 0 = +bias, Q-cols(<192) scaled by SCALE -> fp16 (qkv)
//      1 = +bias, GELU -> fp16 (fc1)
//      2 = +bias, scatter window->token, +resid -> g_h fp32; then fused LN2 -> g_ln216 fp16
//          (requires gridDim.x == 1, i.e. Nc == 192)
#define A_STAGE 10240
#define B_STAGE 15360
#define GSMEM   (3 * (A_STAGE + B_STAGE))
template <int EPI>
__global__ void __launch_bounds__(192)
gemm_wide(const __half* __restrict__ A, const __half* __restrict__ Wt,
          const float* __restrict__ bias, const float* __restrict__ resid,
          const float* __restrict__ lng, const float* __restrict__ lnb,
          void* __restrict__ Cout, int Nc, int K) {
    extern __shared__ __align__(16) char smem[];
    const int tid  = threadIdx.x;
    const int wid  = tid >> 5, lane = tid & 31;
    const int gp   = lane >> 2, tg = lane & 3;
    const int m0   = blockIdx.y << 7;
    const int n0   = blockIdx.x * 192;
    const int wm   = (wid & 1) << 6;    // 0/64
    const int wn   = (wid >> 1) << 6;   // 0/64/128

    float acc[4][8][4];
    #pragma unroll
    for (int i = 0; i < 4; i++)
        #pragma unroll
        for (int j = 0; j < 8; j++)
            #pragma unroll
            for (int e = 0; e < 4; e++) acc[i][j][e] = 0.0f;

    const __half* Ap = A + (size_t)(m0 + tid) * K;         // valid for tid<128
    const __half* Wp = Wt + (size_t)(n0 + tid) * K;

    const uint32_t sA = smem_u32(smem);
    const uint32_t sB = sA + 3 * A_STAGE;
    const uint32_t aDst0 = sA + tid * 80;
    const uint32_t bDst0 = sB + tid * 80;

    const int aRow  = lane & 15;
    const int aCol8 = (lane >> 4) << 3;
    const int bRow  = ((lane & 16) >> 1) + (lane & 7);
    const int bCol8 = lane & 8;
    const uint32_t aOff = ((wm + aRow) * 40 + aCol8) << 1;
    const uint32_t bOff = ((wn + bRow) * 40 + bCol8) << 1;

    const int nc = K >> 5;

#define PREFETCH(ck, st) do {                                            \
        const __half* Ag_ = Ap + (ck) * 32;                              \
        const __half* Wg_ = Wp + (ck) * 32;                              \
        uint32_t aD_ = aDst0 + (st) * A_STAGE;                           \
        uint32_t bD_ = bDst0 + (st) * B_STAGE;                           \
        if (tid < 128) {                                                 \
            cpa16(aD_,      Ag_);      cpa16(aD_ + 16, Ag_ + 8);         \
            cpa16(aD_ + 32, Ag_ + 16); cpa16(aD_ + 48, Ag_ + 24);        \
        }                                                                \
        cpa16(bD_,      Wg_);      cpa16(bD_ + 16, Wg_ + 8);             \
        cpa16(bD_ + 32, Wg_ + 16); cpa16(bD_ + 48, Wg_ + 24);            \
        asm volatile("cp.async.commit_group;" ::: "memory");             \
    } while (0)

    PREFETCH(0, 0);
    PREFETCH(1, 1);

    for (int c = 0; c < nc; c++) {
        const int buf = c % 3;
        if (c + 1 < nc) asm volatile("cp.async.wait_group 1;" ::: "memory");
        else            asm volatile("cp.async.wait_group 0;" ::: "memory");
        __syncthreads();
        if (c + 2 < nc) PREFETCH(c + 2, (c + 2) % 3);

        const uint32_t aBase = sA + buf * A_STAGE + aOff;
        const uint32_t bBase = sB + buf * B_STAGE + bOff;
        #pragma unroll
        for (int kk = 0; kk < 2; kk++) {
            uint32_t af[4][4];
            #pragma unroll
            for (int i = 0; i < 4; i++)
                ldsm4(af[i][0], af[i][1], af[i][2], af[i][3],
                      aBase + ((i * 16 * 40 + kk * 16) << 1));
            uint32_t bf[16];
            #pragma unroll
            for (int j2 = 0; j2 < 4; j2++)
                ldsm4(bf[j2 * 4], bf[j2 * 4 + 1], bf[j2 * 4 + 2], bf[j2 * 4 + 3],
                      bBase + ((j2 * 16 * 40 + kk * 16) << 1));
            #pragma unroll
            for (int i = 0; i < 4; i++)
                #pragma unroll
                for (int j = 0; j < 8; j++)
                    mma_f16(acc[i][j], af[i], &bf[j * 2]);
        }
        __syncthreads();
    }
#undef PREFETCH

    if constexpr (EPI == 2) {
        // ---- proj epilogue: h = acc+bias+resid (scattered, fp32) then fused LN2 ----
        __shared__ float lnp[128][3][4][2];   // [rowLocal][wn-group][tg][sum,sq]
        __shared__ float lnm[128][2];         // [rowLocal][mean,inv]
        const int wnIdx = wid >> 1;
        #pragma unroll
        for (int i = 0; i < 4; i++) {
            #pragma unroll
            for (int half = 0; half < 2; half++) {
                const int rL  = wm + (i << 4) + gp + (half << 3);
                const int row = m0 + rL;
                int wi2 = row / Nn, nn2 = row - wi2 * Nn;
                int bi = wi2 >> 6, wl = wi2 & 63;
                int wr = wl >> 3, wc = wl & 7;
                int rr = DIV7(nn2), cc = nn2 - rr * 7;
                int hd = (wr * 7 + rr + SS) % Hh;
                int wd = (wc * 7 + cc + SS) % Ww;
                size_t tok = (size_t)bi * (Hh * Ww) + hd * Ww + wd;
                size_t rowoff = tok * Cc;
                float psum = 0.0f, psq = 0.0f;
                #pragma unroll
                for (int j = 0; j < 8; j++) {
                    const int ncol = wn + (j << 3) + (tg << 1);
                    float v0 = acc[i][j][half * 2 + 0] + bias[ncol + 0] + resid[rowoff + ncol + 0];
                    float v1 = acc[i][j][half * 2 + 1] + bias[ncol + 1] + resid[rowoff + ncol + 1];
                    *(float2*)(g_h + rowoff + ncol) = make_float2(v0, v1);
                    acc[i][j][half * 2 + 0] = v0;
                    acc[i][j][half * 2 + 1] = v1;
                    psum += v0 + v1;
                    psq  += v0 * v0 + v1 * v1;
                }
                lnp[rL][wnIdx][tg][0] = psum;
                lnp[rL][wnIdx][tg][1] = psq;
            }
        }
        __syncthreads();
        if (tid < 128) {
            float sum = 0.0f, sq = 0.0f;
            #pragma unroll
            for (int w = 0; w < 3; w++)
                #pragma unroll
                for (int t4 = 0; t4 < 4; t4++) {
                    sum += lnp[tid][w][t4][0];
                    sq  += lnp[tid][w][t4][1];
                }
            float mean = sum * (1.0f / Cc);
            float var  = sq * (1.0f / Cc) - mean * mean;
            lnm[tid][0] = mean;
            lnm[tid][1] = rsqrtf(var + 1e-5f);
        }
        __syncthreads();
        #pragma unroll
        for (int i = 0; i < 4; i++) {
            #pragma unroll
            for (int half = 0; half < 2; half++) {
                const int rL  = wm + (i << 4) + gp + (half << 3);
                const int row = m0 + rL;
                int wi2 = row / Nn, nn2 = row - wi2 * Nn;
                int bi = wi2 >> 6, wl = wi2 & 63;
                int wr = wl >> 3, wc = wl & 7;
                int rr = DIV7(nn2), cc = nn2 - rr * 7;
                int hd = (wr * 7 + rr + SS) % Hh;
                int wd = (wc * 7 + cc + SS) % Ww;
                size_t tok = (size_t)bi * (Hh * Ww) + hd * Ww + wd;
                const float mean = lnm[rL][0], inv = lnm[rL][1];
                __half* op = g_ln216 + tok * Cc;
                #pragma unroll
                for (int j = 0; j < 8; j++) {
                    const int ncol = wn + (j << 3) + (tg << 1);
                    float v0 = (acc[i][j][half * 2 + 0] - mean) * inv * lng[ncol + 0] + lnb[ncol + 0];
                    float v1 = (acc[i][j][half * 2 + 1] - mean) * inv * lng[ncol + 1] + lnb[ncol + 1];
                    *(__half2*)(op + ncol) = __floats2half2_rn(v0, v1);
                }
            }
        }
    } else {
        #pragma unroll
        for (int i = 0; i < 4; i++) {
            #pragma unroll
            for (int half = 0; half < 2; half++) {
                const int row = m0 + wm + (i << 4) + gp + (half << 3);
                size_t rowoff = (size_t)row * Nc;
                #pragma unroll
                for (int j = 0; j < 8; j++) {
                    const int ncol = n0 + wn + (j << 3) + (tg << 1);
                    float v0 = acc[i][j][half * 2 + 0] + bias[ncol + 0];
                    float v1 = acc[i][j][half * 2 + 1] + bias[ncol + 1];
                    if (EPI == 0 && ncol < Cc) { v0 *= SCALE; v1 *= SCALE; }
                    if (EPI == 1) {
                        v0 = 0.5f * v0 * (1.0f + erff(v0 * 0.70710678118654752f));
                        v1 = 0.5f * v1 * (1.0f + erff(v1 * 0.70710678118654752f));
                    }
                    *(__half2*)((__half*)Cout + rowoff + ncol) = __floats2half2_rn(v0, v1);
                }
            }
        }
    }
}

// ---------------- narrow fp16 TC GEMM (fc2): BM=128, BN=64, BK=32; 128 thr, 2-stage ----------------
// epilogue: +bias +resid -> fp32
__global__ void __launch_bounds__(128)
gemm_n64(const __half* __restrict__ A, const __half* __restrict__ Wt,
         const float* __restrict__ bias, const float* __restrict__ resid,
         float* __restrict__ Cout, int Nc, int K) {
    __shared__ __half As[2][128 * 40];
    __shared__ __half Bs[2][64 * 40];

    const int tid  = threadIdx.x;
    const int wid  = tid >> 5, lane = tid & 31;
    const int gp   = lane >> 2, tg = lane & 3;
    const int m0   = blockIdx.y << 7;
    const int n0   = blockIdx.x << 6;
    const int wm   = (wid & 1) << 6;
    const int wn   = (wid >> 1) << 5;

    float acc[4][4][4];
    #pragma unroll
    for (int i = 0; i < 4; i++)
        #pragma unroll
        for (int j = 0; j < 4; j++)
            #pragma unroll
            for (int e = 0; e < 4; e++) acc[i][j][e] = 0.0f;

    const __half* Ap = A + (size_t)(m0 + tid) * K;
    const int bRowL  = tid >> 1, bQ = tid & 1;
    const __half* Wp = Wt + (size_t)(n0 + bRowL) * K + bQ * 16;

    const uint32_t sA = smem_u32(As), sB = smem_u32(Bs);
    const uint32_t aDst0 = sA + tid * 80;
    const uint32_t bDst0 = sB + (bRowL * 40 + bQ * 16) * 2;

    const int aRow  = lane & 15;
    const int aCol8 = (lane >> 4) << 3;
    const int bRow  = ((lane & 16) >> 1) + (lane & 7);
    const int bCol8 = lane & 8;
    const uint32_t aOff = ((wm + aRow) * 40 + aCol8) << 1;
    const uint32_t bOff = ((wn + bRow) * 40 + bCol8) << 1;

    const int nc = K >> 5;

    #pragma unroll
    for (int s = 0; s < 4; s++) cpa16(aDst0 + s * 16, Ap + s * 8);
    cpa16(bDst0, Wp);
    cpa16(bDst0 + 16, Wp + 8);
    asm volatile("cp.async.commit_group;" ::: "memory");

    for (int c = 0; c < nc; c++) {
        const int buf = c & 1;
        if (c + 1 < nc) {
            const int nb = (c + 1) & 1;
            const uint32_t aD = aDst0 + nb * (128 * 80);
            const uint32_t bD = bDst0 + nb * (64 * 80);
            const __half* Ag = Ap + (c + 1) * 32;
            const __half* Wg = Wp + (c + 1) * 32;
            #pragma unroll
            for (int s = 0; s < 4; s++) cpa16(aD + s * 16, Ag + s * 8);
            cpa16(bD, Wg);
            cpa16(bD + 16, Wg + 8);
            asm volatile("cp.async.commit_group;" ::: "memory");
            asm volatile("cp.async.wait_group 1;" ::: "memory");
        } else {
            asm volatile("cp.async.wait_group 0;" ::: "memory");
        }
        __syncthreads();

        const uint32_t aBase = sA + buf * (128 * 80) + aOff;
        const uint32_t bBase = sB + buf * (64 * 80) + bOff;
        #pragma unroll
        for (int kk = 0; kk < 2; kk++) {
            uint32_t af[4][4];
            #pragma unroll
            for (int i = 0; i < 4; i++)
                ldsm4(af[i][0], af[i][1], af[i][2], af[i][3],
                      aBase + ((i * 16 * 40 + kk * 16) << 1));
            uint32_t bf[4][2];
            ldsm4(bf[0][0], bf[0][1], bf[1][0], bf[1][1], bBase + ((kk * 16) << 1));
            ldsm4(bf[2][0], bf[2][1], bf[3][0], bf[3][1], bBase + ((16 * 40 + kk * 16) << 1));
            #pragma unroll
            for (int i = 0; i < 4; i++)
                #pragma unroll
                for (int j = 0; j < 4; j++)
                    mma_f16(acc[i][j], af[i], bf[j]);
        }
        __syncthreads();
    }

    #pragma unroll
    for (int i = 0; i < 4; i++) {
        #pragma unroll
        for (int half = 0; half < 2; half++) {
            const int row = m0 + wm + (i << 4) + gp + (half << 3);
            size_t rowoff = (size_t)row * Nc;
            #pragma unroll
            for (int j = 0; j < 4; j++) {
                const int ncol = n0 + wn + (j << 3) + (tg << 1);
                float v0 = acc[i][j][half * 2 + 0] + bias[ncol + 0] + resid[rowoff + ncol + 0];
                float v1 = acc[i][j][half * 2 + 1] + bias[ncol + 1] + resid[rowoff + ncol + 1];
                *(float2*)(Cout + rowoff + ncol) = make_float2(v0, v1);
            }
        }
    }
}

// ---------------- tensor-core window attention: block = (window, head), 128 thr ----------------
__global__ void __launch_bounds__(128)
attn_k() {
    __shared__ __half Qs[64 * 40];
    __shared__ __half Ks[64 * 40];
    __shared__ __half Vt[32 * 72];

    const int wi = blockIdx.x;
    const int nh = blockIdx.y;
    const int tid = threadIdx.x;
    const int wid = tid >> 5, lane = tid & 31;
    const int gp = lane >> 2, tg = lane & 3;

    const int wl = wi & 63;
    const int cls = (((wl >> 3) == 7) ? 2 : 0) | (((wl & 7) == 7) ? 1 : 0);
    const float* tp = g_tab + (cls * NHd + nh) * 4096;

    for (int idx = tid; idx < 64 * 4; idx += 128) {
        int row = idx >> 2, seg = idx & 3;
        uint4 zq = make_uint4(0, 0, 0, 0), zk = zq;
        if (row < Nn) {
            const __half* base = g_qkv16 + (size_t)(wi * Nn + row) * (3 * Cc) + nh * HD + seg * 8;
            zq = *(const uint4*)(base);
            zk = *(const uint4*)(base + Cc);
        }
        *(uint4*)(Qs + row * 40 + seg * 8) = zq;
        *(uint4*)(Ks + row * 40 + seg * 8) = zk;
    }
    for (int idx = tid; idx < 64 * 16; idx += 128) {
        int row = idx >> 4, p = idx & 15;
        __half2 v = __float2half2_rn(0.0f);
        if (row < Nn)
            v = *(const __half2*)(g_qkv16 + (size_t)(wi * Nn + row) * (3 * Cc) + 2 * Cc + nh * HD + 2 * p);
        Vt[(2 * p) * 72 + row]     = __low2half(v);
        Vt[(2 * p + 1) * 72 + row] = __high2half(v);
    }

    const int rowL = wid * 16 + gp, rowH = rowL + 8;
    float st[8][4];
    #pragma unroll
    for (int j = 0; j < 8; j++) {
        float2 vL = *(const float2*)(tp + rowL * 64 + j * 8 + tg * 2);
        float2 vH = *(const float2*)(tp + rowH * 64 + j * 8 + tg * 2);
        st[j][0] = vL.x; st[j][1] = vL.y;
        st[j][2] = vH.x; st[j][3] = vH.y;
    }
    __syncthreads();

    const int aRow  = lane & 15;
    const int aCol8 = (lane >> 4) << 3;
    const int bRow  = ((lane & 16) >> 1) + (lane & 7);
    const int bCol8 = lane & 8;
    const uint32_t qBase = smem_u32(Qs) + (((wid * 16 + aRow) * 40 + aCol8) << 1);
    const uint32_t kBase = smem_u32(Ks) + ((bRow * 40 + bCol8) << 1);

    #pragma unroll
    for (int kk = 0; kk < 2; kk++) {
        uint32_t af[4];
        ldsm4(af[0], af[1], af[2], af[3], qBase + (kk * 16 << 1));
        #pragma unroll
        for (int j2 = 0; j2 < 4; j2++) {
            uint32_t bf[2][2];
            ldsm4(bf[0][0], bf[0][1], bf[1][0], bf[1][1],
                  kBase + ((j2 * 16 * 40 + kk * 16) << 1));
            mma_f16(st[2 * j2],     af, bf[0]);
            mma_f16(st[2 * j2 + 1], af, bf[1]);
        }
    }

    #pragma unroll
    for (int hrow = 0; hrow < 2; hrow++) {
        float mx = -1e30f;
        #pragma unroll
        for (int j = 0; j < 8; j++) {
            mx = fmaxf(mx, st[j][hrow * 2]);
            mx = fmaxf(mx, st[j][hrow * 2 + 1]);
        }
        mx = fmaxf(mx, __shfl_xor_sync(0xffffffffu, mx, 1));
        mx = fmaxf(mx, __shfl_xor_sync(0xffffffffu, mx, 2));
        float sm = 0.0f;
        #pragma unroll
        for (int j = 0; j < 8; j++) {
            #pragma unroll
            for (int e = 0; e < 2; e++) {
                float ev = __expf(st[j][hrow * 2 + e] - mx);
                st[j][hrow * 2 + e] = ev;
                sm += ev;
            }
        }
        sm += __shfl_xor_sync(0xffffffffu, sm, 1);
        sm += __shfl_xor_sync(0xffffffffu, sm, 2);
        float inv = 1.0f / sm;
        #pragma unroll
        for (int j = 0; j < 8; j++) {
            st[j][hrow * 2] *= inv;
            st[j][hrow * 2 + 1] *= inv;
        }
    }

    float o[4][4];
    #pragma unroll
    for (int jt = 0; jt < 4; jt++)
        #pragma unroll
        for (int e = 0; e < 4; e++) o[jt][e] = 0.0f;

    const uint32_t vBase = smem_u32(Vt) + ((bRow * 72 + bCol8) << 1);
    #pragma unroll
    for (int kk = 0; kk < 4; kk++) {
        uint32_t a[4];
        a[0] = h2u(st[2 * kk][0],     st[2 * kk][1]);
        a[1] = h2u(st[2 * kk][2],     st[2 * kk][3]);
        a[2] = h2u(st[2 * kk + 1][0], st[2 * kk + 1][1]);
        a[3] = h2u(st[2 * kk + 1][2], st[2 * kk + 1][3]);
        #pragma unroll
        for (int jj2 = 0; jj2 < 2; jj2++) {
            uint32_t bf[2][2];
            ldsm4(bf[0][0], bf[0][1], bf[1][0], bf[1][1],
                  vBase + ((jj2 * 16 * 72 + kk * 16) << 1));
            mma_f16(o[2 * jj2],     a, bf[0]);
            mma_f16(o[2 * jj2 + 1], a, bf[1]);
        }
    }

    __half* outp = g_attn16 + (size_t)wi * Nn * Cc + nh * HD;
    #pragma unroll
    for (int hrow = 0; hrow < 2; hrow++) {
        const int rI = hrow ? rowH : rowL;
        if (rI < Nn) {
            __half* rp = outp + (size_t)rI * Cc;
            #pragma unroll
            for (int jt = 0; jt < 4; jt++)
                *(__half2*)(rp + jt * 8 + tg * 2) =
                    __floats2half2_rn(o[jt][hrow * 2], o[jt][hrow * 2 + 1]);
        }
    }
}

// ---------------- host ----------------
extern "C" void kernel_launch(void* const* d_in, const int* in_sizes, int n_in,
                              void* d_out, int out_size) {
    const float* x     = (const float*)d_in[0];
    const float* n1g   = (const float*)d_in[1];
    const float* n1b   = (const float*)d_in[2];
    const float* qkvw  = (const float*)d_in[3];
    const float* qkvb  = (const float*)d_in[4];
    const float* projw = (const float*)d_in[5];
    const float* projb = (const float*)d_in[6];
    const float* rpb   = (const float*)d_in[7];
    const float* n2g   = (const float*)d_in[8];
    const float* n2b   = (const float*)d_in[9];
    const float* fc1w  = (const float*)d_in[10];
    const float* fc1b  = (const float*)d_in[11];
    const float* fc2w  = (const float*)d_in[12];
    const float* fc2b  = (const float*)d_in[13];
    float* out = (float*)d_out;

    static __half *p_xw16 = nullptr, *p_qkv16, *p_attn16, *p_ln216, *p_act16,
                  *p_qkvw16, *p_projw16, *p_fc1w16, *p_fc2w16;
    static float *p_h;
    if (!p_xw16) {
        cudaGetSymbolAddress((void**)&p_xw16,   g_xw16);
        cudaGetSymbolAddress((void**)&p_qkv16,  g_qkv16);
        cudaGetSymbolAddress((void**)&p_attn16, g_attn16);
        cudaGetSymbolAddress((void**)&p_h,      g_h);
        cudaGetSymbolAddress((void**)&p_ln216,  g_ln216);
        cudaGetSymbolAddress((void**)&p_act16,  g_act16);
        cudaGetSymbolAddress((void**)&p_qkvw16, g_qkvw16);
        cudaGetSymbolAddress((void**)&p_projw16,g_projw16);
        cudaGetSymbolAddress((void**)&p_fc1w16, g_fc1w16);
        cudaGetSymbolAddress((void**)&p_fc2w16, g_fc2w16);
        cudaFuncSetAttribute(gemm_wide<0>, cudaFuncAttributeMaxDynamicSharedMemorySize, GSMEM);
        cudaFuncSetAttribute(gemm_wide<1>, cudaFuncAttributeMaxDynamicSharedMemorySize, GSMEM);
        cudaFuncSetAttribute(gemm_wide<2>, cudaFuncAttributeMaxDynamicSharedMemorySize, GSMEM);
    }

    // 0) weight conversion + bias/mask tables
    const int CV = 3 * Cc * Cc + Cc * Cc + HID * Cc + Cc * HID;
    cvt_all<<<(CV + 255) / 256, 256>>>(qkvw, projw, fc1w, fc2w);
    build_tab<<<24, 256>>>(rpb);

    // 1) LN1 + roll + window partition -> fp16
    ln1_shift_part<<<TOK / 8, 256>>>(x, n1g, n1b);
    // 2) QKV GEMM (Q prescaled by SCALE in epilogue)
    gemm_wide<0><<<dim3(3, TOK / 128), 192, GSMEM>>>(p_xw16, p_qkvw16, qkvb, nullptr, nullptr, nullptr, p_qkv16, 3 * Cc, Cc);
    // 3) window attention
    attn_k<<<dim3(NWTOT, NHd), 128>>>();
    // 4) proj GEMM + scatter + residual -> h, fused LN2 -> ln216
    gemm_wide<2><<<dim3(1, TOK / 128), 192, GSMEM>>>(p_attn16, p_projw16, projb, x, n2g, n2b, p_h, Cc, Cc);
    // 5) FC1 + GELU -> fp16
    gemm_wide<1><<<dim3(4, TOK / 128), 192, GSMEM>>>(p_ln216, p_fc1w16, fc1b, nullptr, nullptr, nullptr, p_act16, HID, Cc);
    // 6) FC2 + residual -> out (narrow tiles, high occupancy)
    gemm_n64<<<dim3(3, TOK / 128), 128>>>(p_act16, p_fc2w16, fc2b, p_h, out, Cc, HID);
}

// round 11
// speedup vs baseline: 1.0012x; 1.0012x over previous
#include <cuda_runtime.h>
#include <cuda_fp16.h>
#include <math.h>
#include <stddef.h>
#include <stdint.h>

#define Bb   32
#define Hh   56
#define Ww   56
#define Cc   192
#define WS   7
#define SS   3
#define NHd  6
#define Nn   49
#define HD   32
#define NWTOT 2048
#define TOK  100352
#define HID  768
#define SCALE 0.17677669529663687f  /* 32^-0.5 */

// ---------------- scratch (device globals; no allocations) ----------------
__device__ __half g_xw16  [(size_t)TOK * Cc];
__device__ __half g_qkv16 [(size_t)TOK * 3 * Cc];
__device__ __half g_attn16[(size_t)TOK * Cc];
__device__ float  g_h     [(size_t)TOK * Cc];
__device__ __half g_ln216 [(size_t)TOK * Cc];
__device__ __half g_act16 [(size_t)TOK * HID];
__device__ __half g_qkvw16[3 * Cc * Cc];
__device__ __half g_projw16[Cc * Cc];
__device__ __half g_fc1w16[HID * Cc];
__device__ __half g_fc2w16[Cc * HID];
__device__ float  g_tab   [24 * 64 * 64];     // (cls*6+nh) x 64 x 64 bias+mask

// ---------------- helpers ----------------
static __device__ __forceinline__ uint32_t smem_u32(const void* p) {
    uint32_t a;
    asm("{ .reg .u64 t; cvta.to.shared.u64 t, %1; cvt.u32.u64 %0, t; }" : "=r"(a) : "l"(p));
    return a;
}
static __device__ __forceinline__ void ldsm4(uint32_t& r0, uint32_t& r1, uint32_t& r2,
                                             uint32_t& r3, uint32_t addr) {
    asm volatile("ldmatrix.sync.aligned.m8n8.x4.shared.b16 {%0,%1,%2,%3}, [%4];"
                 : "=r"(r0), "=r"(r1), "=r"(r2), "=r"(r3) : "r"(addr));
}
static __device__ __forceinline__ void mma_f16(float* c, const uint32_t* a, const uint32_t* b) {
    asm volatile(
        "mma.sync.aligned.m16n8k16.row.col.f32.f16.f16.f32 "
        "{%0,%1,%2,%3}, {%4,%5,%6,%7}, {%8,%9}, {%0,%1,%2,%3};"
        : "+f"(c[0]), "+f"(c[1]), "+f"(c[2]), "+f"(c[3])
        : "r"(a[0]), "r"(a[1]), "r"(a[2]), "r"(a[3]), "r"(b[0]), "r"(b[1]));
}
static __device__ __forceinline__ void cpa16(uint32_t dst, const void* src) {
    asm volatile("cp.async.ca.shared.global [%0], [%1], 16;" :: "r"(dst), "l"(src));
}
static __device__ __forceinline__ uint32_t h2u(float a, float b) {
    __half2 h = __floats2half2_rn(a, b);
    return *(uint32_t*)&h;
}
#define DIV7(u) (((u) * 9363) >> 16)

static __device__ __forceinline__ float wsum(float v) {
    #pragma unroll
    for (int o = 16; o; o >>= 1) v += __shfl_xor_sync(0xffffffffu, v, o);
    return v;
}

// ---------------- fused weight conversion ----------------
__global__ void cvt_all(const float* __restrict__ qkvw, const float* __restrict__ projw,
                        const float* __restrict__ fc1w, const float* __restrict__ fc2w) {
    int i = blockIdx.x * 256 + threadIdx.x;
    const int S0 = 3 * Cc * Cc, S1 = Cc * Cc, S2 = HID * Cc, S3 = Cc * HID;
    if (i < S0) { g_qkvw16[i] = __float2half(qkvw[i]); return; }
    i -= S0;
    if (i < S1) { g_projw16[i] = __float2half(projw[i]); return; }
    i -= S1;
    if (i < S2) { g_fc1w16[i] = __float2half(fc1w[i]); return; }
    i -= S2;
    if (i < S3) { g_fc2w16[i] = __float2half(fc2w[i]); }
}

// ---------------- bias+mask tables: 4 window classes x 6 heads x 64x64 ----------------
__global__ void build_tab(const float* __restrict__ rpb) {
    int cls = blockIdx.x / NHd, nh = blockIdx.x - cls * NHd;
    int lastR = (cls >> 1) & 1, lastC = cls & 1;
    float* tp = g_tab + blockIdx.x * 4096;
    for (int idx = threadIdx.x; idx < 4096; idx += 256) {
        int rI = idx >> 6, m = idx & 63;
        float v;
        if (rI >= Nn) v = 0.0f;
        else if (m >= Nn) v = -1e30f;
        else {
            int r1 = DIV7(rI), c1 = rI - r1 * 7;
            int r2 = DIV7(m),  c2 = m  - r2 * 7;
            float bias = rpb[((r1 - r2 + 6) * 13 + (c1 - c2 + 6)) * NHd + nh];
            int rg1 = (lastR ? (r1 < 4 ? 1 : 2) : 0) * 3 + (lastC ? (c1 < 4 ? 1 : 2) : 0);
            int rg2 = (lastR ? (r2 < 4 ? 1 : 2) : 0) * 3 + (lastC ? (c2 < 4 ? 1 : 2) : 0);
            v = bias + ((rg1 == rg2) ? 0.0f : -100.0f);
        }
        tp[idx] = v;
    }
}

// ---------------- LN1 + roll(-3,-3) + window partition (warp per token) ----------------
__global__ void __launch_bounds__(256)
ln1_shift_part(const float* __restrict__ x, const float* __restrict__ g,
               const float* __restrict__ b) {
    int t = blockIdx.x * 8 + (threadIdx.x >> 5);
    int lane = threadIdx.x & 31;
    int wi = t / Nn, n = t - wi * Nn;
    int bi = wi >> 6, wl = wi & 63;
    int wr = wl >> 3, wc = wl & 7;
    int r = DIV7(n), c2 = n - r * 7;
    int hsrc = (wr * 7 + r + SS) % Hh;
    int wsrc = (wc * 7 + c2 + SS) % Ww;
    const float* row = x + ((size_t)bi * (Hh * Ww) + hsrc * Ww + wsrc) * Cc;
    float v[6];
    float s = 0.0f;
    #pragma unroll
    for (int j = 0; j < 6; j++) { v[j] = row[lane + 32 * j]; s += v[j]; }
    float mean = wsum(s) * (1.0f / Cc);
    float q = 0.0f;
    #pragma unroll
    for (int j = 0; j < 6; j++) { v[j] -= mean; q += v[j] * v[j]; }
    float inv = rsqrtf(wsum(q) * (1.0f / Cc) + 1e-5f);
    __half* o = g_xw16 + (size_t)t * Cc;
    #pragma unroll
    for (int j = 0; j < 6; j++) {
        int c = lane + 32 * j;
        o[c] = __float2half(v[j] * inv * g[c] + b[c]);
    }
}

// ---------------- LN2 (warp per token) ----------------
__global__ void __launch_bounds__(256)
ln2_k(const float* __restrict__ g, const float* __restrict__ b) {
    int t = blockIdx.x * 8 + (threadIdx.x >> 5);
    int lane = threadIdx.x & 31;
    const float* row = g_h + (size_t)t * Cc;
    float v[6];
    float s = 0.0f;
    #pragma unroll
    for (int j = 0; j < 6; j++) { v[j] = row[lane + 32 * j]; s += v[j]; }
    float mean = wsum(s) * (1.0f / Cc);
    float q = 0.0f;
    #pragma unroll
    for (int j = 0; j < 6; j++) { v[j] -= mean; q += v[j] * v[j]; }
    float inv = rsqrtf(wsum(q) * (1.0f / Cc) + 1e-5f);
    __half* o = g_ln216 + (size_t)t * Cc;
    #pragma unroll
    for (int j = 0; j < 6; j++) {
        int c = lane + 32 * j;
        o[c] = __float2half(v[j] * inv * g[c] + b[c]);
    }
}

// ---------------- wide fp16 TC GEMM: BM=128, BN=192, BK=32; 192 thr (6 warps 2x3) ----------------
// for LARGE-grid wide-N GEMMs (qkv, fc1).
// EPI: 0 = +bias, Q-cols(<192) scaled by SCALE -> fp16 (qkv)
//      1 = +bias, GELU -> fp16 (fc1)
#define A_STAGE 10240
#define B_STAGE 15360
#define GSMEM   (3 * (A_STAGE + B_STAGE))
template <int EPI>
__global__ void __launch_bounds__(192)
gemm_wide(const __half* __restrict__ A, const __half* __restrict__ Wt,
          const float* __restrict__ bias, __half* __restrict__ Cout, int Nc, int K) {
    extern __shared__ __align__(16) char smem[];
    const int tid  = threadIdx.x;
    const int wid  = tid >> 5, lane = tid & 31;
    const int gp   = lane >> 2, tg = lane & 3;
    const int m0   = blockIdx.y << 7;
    const int n0   = blockIdx.x * 192;
    const int wm   = (wid & 1) << 6;    // 0/64
    const int wn   = (wid >> 1) << 6;   // 0/64/128

    float acc[4][8][4];
    #pragma unroll
    for (int i = 0; i < 4; i++)
        #pragma unroll
        for (int j = 0; j < 8; j++)
            #pragma unroll
            for (int e = 0; e < 4; e++) acc[i][j][e] = 0.0f;

    const __half* Ap = A + (size_t)(m0 + tid) * K;         // valid for tid<128
    const __half* Wp = Wt + (size_t)(n0 + tid) * K;

    const uint32_t sA = smem_u32(smem);
    const uint32_t sB = sA + 3 * A_STAGE;
    const uint32_t aDst0 = sA + tid * 80;
    const uint32_t bDst0 = sB + tid * 80;

    const int aRow  = lane & 15;
    const int aCol8 = (lane >> 4) << 3;
    const int bRow  = ((lane & 16) >> 1) + (lane & 7);
    const int bCol8 = lane & 8;
    const uint32_t aOff = ((wm + aRow) * 40 + aCol8) << 1;
    const uint32_t bOff = ((wn + bRow) * 40 + bCol8) << 1;

    const int nc = K >> 5;

#define PREFETCH(ck, st) do {                                            \
        const __half* Ag_ = Ap + (ck) * 32;                              \
        const __half* Wg_ = Wp + (ck) * 32;                              \
        uint32_t aD_ = aDst0 + (st) * A_STAGE;                           \
        uint32_t bD_ = bDst0 + (st) * B_STAGE;                           \
        if (tid < 128) {                                                 \
            cpa16(aD_,      Ag_);      cpa16(aD_ + 16, Ag_ + 8);         \
            cpa16(aD_ + 32, Ag_ + 16); cpa16(aD_ + 48, Ag_ + 24);        \
        }                                                                \
        cpa16(bD_,      Wg_);      cpa16(bD_ + 16, Wg_ + 8);             \
        cpa16(bD_ + 32, Wg_ + 16); cpa16(bD_ + 48, Wg_ + 24);            \
        asm volatile("cp.async.commit_group;" ::: "memory");             \
    } while (0)

    PREFETCH(0, 0);
    PREFETCH(1, 1);

    for (int c = 0; c < nc; c++) {
        const int buf = c % 3;
        if (c + 1 < nc) asm volatile("cp.async.wait_group 1;" ::: "memory");
        else            asm volatile("cp.async.wait_group 0;" ::: "memory");
        __syncthreads();
        if (c + 2 < nc) PREFETCH(c + 2, (c + 2) % 3);

        const uint32_t aBase = sA + buf * A_STAGE + aOff;
        const uint32_t bBase = sB + buf * B_STAGE + bOff;
        #pragma unroll
        for (int kk = 0; kk < 2; kk++) {
            uint32_t af[4][4];
            #pragma unroll
            for (int i = 0; i < 4; i++)
                ldsm4(af[i][0], af[i][1], af[i][2], af[i][3],
                      aBase + ((i * 16 * 40 + kk * 16) << 1));
            uint32_t bf[16];
            #pragma unroll
            for (int j2 = 0; j2 < 4; j2++)
                ldsm4(bf[j2 * 4], bf[j2 * 4 + 1], bf[j2 * 4 + 2], bf[j2 * 4 + 3],
                      bBase + ((j2 * 16 * 40 + kk * 16) << 1));
            #pragma unroll
            for (int i = 0; i < 4; i++)
                #pragma unroll
                for (int j = 0; j < 8; j++)
                    mma_f16(acc[i][j], af[i], &bf[j * 2]);
        }
        __syncthreads();
    }
#undef PREFETCH

    #pragma unroll
    for (int i = 0; i < 4; i++) {
        #pragma unroll
        for (int half = 0; half < 2; half++) {
            const int row = m0 + wm + (i << 4) + gp + (half << 3);
            size_t rowoff = (size_t)row * Nc;
            #pragma unroll
            for (int j = 0; j < 8; j++) {
                const int ncol = n0 + wn + (j << 3) + (tg << 1);
                float v0 = acc[i][j][half * 2 + 0] + bias[ncol + 0];
                float v1 = acc[i][j][half * 2 + 1] + bias[ncol + 1];
                if (EPI == 0 && ncol < Cc) { v0 *= SCALE; v1 *= SCALE; }
                if (EPI == 1) {
                    v0 = 0.5f * v0 * (1.0f + erff(v0 * 0.70710678118654752f));
                    v1 = 0.5f * v1 * (1.0f + erff(v1 * 0.70710678118654752f));
                }
                *(__half2*)(Cout + rowoff + ncol) = __floats2half2_rn(v0, v1);
            }
        }
    }
}

// ---------------- narrow fp16 TC GEMM: BM=128, BN=64, BK=32; 128 thr, 2-stage ----------------
// for Nc=192 GEMMs (proj, fc2): high occupancy (~5 CTAs/SM).
// EPI: 2 = +bias, scatter window->token, +resid -> fp32 (proj)
//      3 = +bias, +resid -> fp32 (fc2)
template <int EPI>
__global__ void __launch_bounds__(128)
gemm_n64(const __half* __restrict__ A, const __half* __restrict__ Wt,
         const float* __restrict__ bias, const float* __restrict__ resid,
         float* __restrict__ Cout, int Nc, int K) {
    __shared__ __half As[2][128 * 40];
    __shared__ __half Bs[2][64 * 40];

    const int tid  = threadIdx.x;
    const int wid  = tid >> 5, lane = tid & 31;
    const int gp   = lane >> 2, tg = lane & 3;
    const int m0   = blockIdx.y << 7;
    const int n0   = blockIdx.x << 6;
    const int wm   = (wid & 1) << 6;
    const int wn   = (wid >> 1) << 5;

    float acc[4][4][4];
    #pragma unroll
    for (int i = 0; i < 4; i++)
        #pragma unroll
        for (int j = 0; j < 4; j++)
            #pragma unroll
            for (int e = 0; e < 4; e++) acc[i][j][e] = 0.0f;

    const __half* Ap = A + (size_t)(m0 + tid) * K;
    const int bRowL  = tid >> 1, bQ = tid & 1;
    const __half* Wp = Wt + (size_t)(n0 + bRowL) * K + bQ * 16;

    const uint32_t sA = smem_u32(As), sB = smem_u32(Bs);
    const uint32_t aDst0 = sA + tid * 80;
    const uint32_t bDst0 = sB + (bRowL * 40 + bQ * 16) * 2;

    const int aRow  = lane & 15;
    const int aCol8 = (lane >> 4) << 3;
    const int bRow  = ((lane & 16) >> 1) + (lane & 7);
    const int bCol8 = lane & 8;
    const uint32_t aOff = ((wm + aRow) * 40 + aCol8) << 1;
    const uint32_t bOff = ((wn + bRow) * 40 + bCol8) << 1;

    const int nc = K >> 5;

    #pragma unroll
    for (int s = 0; s < 4; s++) cpa16(aDst0 + s * 16, Ap + s * 8);
    cpa16(bDst0, Wp);
    cpa16(bDst0 + 16, Wp + 8);
    asm volatile("cp.async.commit_group;" ::: "memory");

    for (int c = 0; c < nc; c++) {
        const int buf = c & 1;
        if (c + 1 < nc) {
            const int nb = (c + 1) & 1;
            const uint32_t aD = aDst0 + nb * (128 * 80);
            const uint32_t bD = bDst0 + nb * (64 * 80);
            const __half* Ag = Ap + (c + 1) * 32;
            const __half* Wg = Wp + (c + 1) * 32;
            #pragma unroll
            for (int s = 0; s < 4; s++) cpa16(aD + s * 16, Ag + s * 8);
            cpa16(bD, Wg);
            cpa16(bD + 16, Wg + 8);
            asm volatile("cp.async.commit_group;" ::: "memory");
            asm volatile("cp.async.wait_group 1;" ::: "memory");
        } else {
            asm volatile("cp.async.wait_group 0;" ::: "memory");
        }
        __syncthreads();

        const uint32_t aBase = sA + buf * (128 * 80) + aOff;
        const uint32_t bBase = sB + buf * (64 * 80) + bOff;
        #pragma unroll
        for (int kk = 0; kk < 2; kk++) {
            uint32_t af[4][4];
            #pragma unroll
            for (int i = 0; i < 4; i++)
                ldsm4(af[i][0], af[i][1], af[i][2], af[i][3],
                      aBase + ((i * 16 * 40 + kk * 16) << 1));
            uint32_t bf[4][2];
            ldsm4(bf[0][0], bf[0][1], bf[1][0], bf[1][1], bBase + ((kk * 16) << 1));
            ldsm4(bf[2][0], bf[2][1], bf[3][0], bf[3][1], bBase + ((16 * 40 + kk * 16) << 1));
            #pragma unroll
            for (int i = 0; i < 4; i++)
                #pragma unroll
                for (int j = 0; j < 4; j++)
                    mma_f16(acc[i][j], af[i], bf[j]);
        }
        __syncthreads();
    }

    #pragma unroll
    for (int i = 0; i < 4; i++) {
        #pragma unroll
        for (int half = 0; half < 2; half++) {
            const int row = m0 + wm + (i << 4) + gp + (half << 3);
            size_t rowoff;
            if (EPI == 2) {
                int wi2 = row / Nn, nn2 = row - wi2 * Nn;
                int bi = wi2 >> 6, wl = wi2 & 63;
                int wr = wl >> 3, wc = wl & 7;
                int rr = DIV7(nn2), cc = nn2 - rr * 7;
                int hd = (wr * 7 + rr + SS) % Hh;
                int wd = (wc * 7 + cc + SS) % Ww;
                rowoff = ((size_t)bi * (Hh * Ww) + hd * Ww + wd) * (size_t)Nc;
            } else {
                rowoff = (size_t)row * Nc;
            }
            #pragma unroll
            for (int j = 0; j < 4; j++) {
                const int ncol = n0 + wn + (j << 3) + (tg << 1);
                float v0 = acc[i][j][half * 2 + 0] + bias[ncol + 0] + resid[rowoff + ncol + 0];
                float v1 = acc[i][j][half * 2 + 1] + bias[ncol + 1] + resid[rowoff + ncol + 1];
                *(float2*)(Cout + rowoff + ncol) = make_float2(v0, v1);
            }
        }
    }
}

// ---------------- tensor-core window attention: block = (window, head), 128 thr ----------------
__global__ void __launch_bounds__(128)
attn_k() {
    __shared__ __half Qs[64 * 40];
    __shared__ __half Ks[64 * 40];
    __shared__ __half Vt[32 * 72];

    const int wi = blockIdx.x;
    const int nh = blockIdx.y;
    const int tid = threadIdx.x;
    const int wid = tid >> 5, lane = tid & 31;
    const int gp = lane >> 2, tg = lane & 3;

    const int wl = wi & 63;
    const int cls = (((wl >> 3) == 7) ? 2 : 0) | (((wl & 7) == 7) ? 1 : 0);
    const float* tp = g_tab + (cls * NHd + nh) * 4096;

    for (int idx = tid; idx < 64 * 4; idx += 128) {
        int row = idx >> 2, seg = idx & 3;
        uint4 zq = make_uint4(0, 0, 0, 0), zk = zq;
        if (row < Nn) {
            const __half* base = g_qkv16 + (size_t)(wi * Nn + row) * (3 * Cc) + nh * HD + seg * 8;
            zq = *(const uint4*)(base);
            zk = *(const uint4*)(base + Cc);
        }
        *(uint4*)(Qs + row * 40 + seg * 8) = zq;
        *(uint4*)(Ks + row * 40 + seg * 8) = zk;
    }
    for (int idx = tid; idx < 64 * 16; idx += 128) {
        int row = idx >> 4, p = idx & 15;
        __half2 v = __float2half2_rn(0.0f);
        if (row < Nn)
            v = *(const __half2*)(g_qkv16 + (size_t)(wi * Nn + row) * (3 * Cc) + 2 * Cc + nh * HD + 2 * p);
        Vt[(2 * p) * 72 + row]     = __low2half(v);
        Vt[(2 * p + 1) * 72 + row] = __high2half(v);
    }

    const int rowL = wid * 16 + gp, rowH = rowL + 8;
    float st[8][4];
    #pragma unroll
    for (int j = 0; j < 8; j++) {
        float2 vL = *(const float2*)(tp + rowL * 64 + j * 8 + tg * 2);
        float2 vH = *(const float2*)(tp + rowH * 64 + j * 8 + tg * 2);
        st[j][0] = vL.x; st[j][1] = vL.y;
        st[j][2] = vH.x; st[j][3] = vH.y;
    }
    __syncthreads();

    const int aRow  = lane & 15;
    const int aCol8 = (lane >> 4) << 3;
    const int bRow  = ((lane & 16) >> 1) + (lane & 7);
    const int bCol8 = lane & 8;
    const uint32_t qBase = smem_u32(Qs) + (((wid * 16 + aRow) * 40 + aCol8) << 1);
    const uint32_t kBase = smem_u32(Ks) + ((bRow * 40 + bCol8) << 1);

    #pragma unroll
    for (int kk = 0; kk < 2; kk++) {
        uint32_t af[4];
        ldsm4(af[0], af[1], af[2], af[3], qBase + (kk * 16 << 1));
        #pragma unroll
        for (int j2 = 0; j2 < 4; j2++) {
            uint32_t bf[2][2];
            ldsm4(bf[0][0], bf[0][1], bf[1][0], bf[1][1],
                  kBase + ((j2 * 16 * 40 + kk * 16) << 1));
            mma_f16(st[2 * j2],     af, bf[0]);
            mma_f16(st[2 * j2 + 1], af, bf[1]);
        }
    }

    #pragma unroll
    for (int hrow = 0; hrow < 2; hrow++) {
        float mx = -1e30f;
        #pragma unroll
        for (int j = 0; j < 8; j++) {
            mx = fmaxf(mx, st[j][hrow * 2]);
            mx = fmaxf(mx, st[j][hrow * 2 + 1]);
        }
        mx = fmaxf(mx, __shfl_xor_sync(0xffffffffu, mx, 1));
        mx = fmaxf(mx, __shfl_xor_sync(0xffffffffu, mx, 2));
        float sm = 0.0f;
        #pragma unroll
        for (int j = 0; j < 8; j++) {
            #pragma unroll
            for (int e = 0; e < 2; e++) {
                float ev = __expf(st[j][hrow * 2 + e] - mx);
                st[j][hrow * 2 + e] = ev;
                sm += ev;
            }
        }
        sm += __shfl_xor_sync(0xffffffffu, sm, 1);
        sm += __shfl_xor_sync(0xffffffffu, sm, 2);
        float inv = 1.0f / sm;
        #pragma unroll
        for (int j = 0; j < 8; j++) {
            st[j][hrow * 2] *= inv;
            st[j][hrow * 2 + 1] *= inv;
        }
    }

    float o[4][4];
    #pragma unroll
    for (int jt = 0; jt < 4; jt++)
        #pragma unroll
        for (int e = 0; e < 4; e++) o[jt][e] = 0.0f;

    const uint32_t vBase = smem_u32(Vt) + ((bRow * 72 + bCol8) << 1);
    #pragma unroll
    for (int kk = 0; kk < 4; kk++) {
        uint32_t a[4];
        a[0] = h2u(st[2 * kk][0],     st[2 * kk][1]);
        a[1] = h2u(st[2 * kk][2],     st[2 * kk][3]);
        a[2] = h2u(st[2 * kk + 1][0], st[2 * kk + 1][1]);
        a[3] = h2u(st[2 * kk + 1][2], st[2 * kk + 1][3]);
        #pragma unroll
        for (int jj2 = 0; jj2 < 2; jj2++) {
            uint32_t bf[2][2];
            ldsm4(bf[0][0], bf[0][1], bf[1][0], bf[1][1],
                  vBase + ((jj2 * 16 * 72 + kk * 16) << 1));
            mma_f16(o[2 * jj2],     a, bf[0]);
            mma_f16(o[2 * jj2 + 1], a, bf[1]);
        }
    }

    __half* outp = g_attn16 + (size_t)wi * Nn * Cc + nh * HD;
    #pragma unroll
    for (int hrow = 0; hrow < 2; hrow++) {
        const int rI = hrow ? rowH : rowL;
        if (rI < Nn) {
            __half* rp = outp + (size_t)rI * Cc;
            #pragma unroll
            for (int jt = 0; jt < 4; jt++)
                *(__half2*)(rp + jt * 8 + tg * 2) =
                    __floats2half2_rn(o[jt][hrow * 2], o[jt][hrow * 2 + 1]);
        }
    }
}

// ---------------- host ----------------
extern "C" void kernel_launch(void* const* d_in, const int* in_sizes, int n_in,
                              void* d_out, int out_size) {
    const float* x     = (const float*)d_in[0];
    const float* n1g   = (const float*)d_in[1];
    const float* n1b   = (const float*)d_in[2];
    const float* qkvw  = (const float*)d_in[3];
    const float* qkvb  = (const float*)d_in[4];
    const float* projw = (const float*)d_in[5];
    const float* projb = (const float*)d_in[6];
    const float* rpb   = (const float*)d_in[7];
    const float* n2g   = (const float*)d_in[8];
    const float* n2b   = (const float*)d_in[9];
    const float* fc1w  = (const float*)d_in[10];
    const float* fc1b  = (const float*)d_in[11];
    const float* fc2w  = (const float*)d_in[12];
    const float* fc2b  = (const float*)d_in[13];
    float* out = (float*)d_out;

    static __half *p_xw16 = nullptr, *p_qkv16, *p_attn16, *p_ln216, *p_act16,
                  *p_qkvw16, *p_projw16, *p_fc1w16, *p_fc2w16;
    static float *p_h;
    if (!p_xw16) {
        cudaGetSymbolAddress((void**)&p_xw16,   g_xw16);
        cudaGetSymbolAddress((void**)&p_qkv16,  g_qkv16);
        cudaGetSymbolAddress((void**)&p_attn16, g_attn16);
        cudaGetSymbolAddress((void**)&p_h,      g_h);
        cudaGetSymbolAddress((void**)&p_ln216,  g_ln216);
        cudaGetSymbolAddress((void**)&p_act16,  g_act16);
        cudaGetSymbolAddress((void**)&p_qkvw16, g_qkvw16);
        cudaGetSymbolAddress((void**)&p_projw16,g_projw16);
        cudaGetSymbolAddress((void**)&p_fc1w16, g_fc1w16);
        cudaGetSymbolAddress((void**)&p_fc2w16, g_fc2w16);
        cudaFuncSetAttribute(gemm_wide<0>, cudaFuncAttributeMaxDynamicSharedMemorySize, GSMEM);
        cudaFuncSetAttribute(gemm_wide<1>, cudaFuncAttributeMaxDynamicSharedMemorySize, GSMEM);
    }

    // 0) weight conversion + bias/mask tables
    const int CV = 3 * Cc * Cc + Cc * Cc + HID * Cc + Cc * HID;
    cvt_all<<<(CV + 255) / 256, 256>>>(qkvw, projw, fc1w, fc2w);
    build_tab<<<24, 256>>>(rpb);

    // 1) LN1 + roll + window partition -> fp16
    ln1_shift_part<<<TOK / 8, 256>>>(x, n1g, n1b);
    // 2) QKV GEMM (wide; Q prescaled by SCALE in epilogue)
    gemm_wide<0><<<dim3(3, TOK / 128), 192, GSMEM>>>(p_xw16, p_qkvw16, qkvb, p_qkv16, 3 * Cc, Cc);
    // 3) window attention
    attn_k<<<dim3(NWTOT, NHd), 128>>>();
    // 4) proj GEMM + scatter + residual -> h (narrow, high occupancy)
    gemm_n64<2><<<dim3(3, TOK / 128), 128>>>(p_attn16, p_projw16, projb, x, p_h, Cc, Cc);
    // 5) LN2 -> fp16
    ln2_k<<<TOK / 8, 256>>>(n2g, n2b);
    // 6) FC1 + GELU -> fp16 (wide)
    gemm_wide<1><<<dim3(4, TOK / 128), 192, GSMEM>>>(p_ln216, p_fc1w16, fc1b, p_act16, HID, Cc);
    // 7) FC2 + residual -> out (narrow, high occupancy)
    gemm_n64<3><<<dim3(3, TOK / 128), 128>>>(p_act16, p_fc2w16, fc2b, p_h, out, Cc, HID);
}

// round 12
// speedup vs baseline: 1.0276x; 1.0264x over previous
#include <cuda_runtime.h>
#include <cuda_fp16.h>
#include <math.h>
#include <stddef.h>
#include <stdint.h>

#define Bb   32
#define Hh   56
#define Ww   56
#define Cc   192
#define WS   7
#define SS   3
#define NHd  6
#define Nn   49
#define HD   32
#define NWTOT 2048
#define TOK  100352
#define HID  768
#define SCALE 0.17677669529663687f  /* 32^-0.5 */

// ---------------- scratch (device globals; no allocations) ----------------
__device__ __half g_xw16  [(size_t)TOK * Cc];
__device__ __half g_qkv16 [(size_t)TOK * 3 * Cc];
__device__ __half g_attn16[(size_t)TOK * Cc];
__device__ float  g_h     [(size_t)TOK * Cc];
__device__ __half g_ln216 [(size_t)TOK * Cc];
__device__ __half g_act16 [(size_t)TOK * HID];
__device__ __half g_qkvw16[3 * Cc * Cc];
__device__ __half g_projw16[Cc * Cc];
__device__ __half g_fc1w16[HID * Cc];
__device__ __half g_fc2w16[Cc * HID];
__device__ float  g_tab   [24 * 64 * 64];     // (cls*6+nh) x 64 x 64 bias+mask

// ---------------- helpers ----------------
static __device__ __forceinline__ uint32_t smem_u32(const void* p) {
    uint32_t a;
    asm("{ .reg .u64 t; cvta.to.shared.u64 t, %1; cvt.u32.u64 %0, t; }" : "=r"(a) : "l"(p));
    return a;
}
static __device__ __forceinline__ void ldsm4(uint32_t& r0, uint32_t& r1, uint32_t& r2,
                                             uint32_t& r3, uint32_t addr) {
    asm volatile("ldmatrix.sync.aligned.m8n8.x4.shared.b16 {%0,%1,%2,%3}, [%4];"
                 : "=r"(r0), "=r"(r1), "=r"(r2), "=r"(r3) : "r"(addr));
}
static __device__ __forceinline__ void mma_f16(float* c, const uint32_t* a, const uint32_t* b) {
    asm volatile(
        "mma.sync.aligned.m16n8k16.row.col.f32.f16.f16.f32 "
        "{%0,%1,%2,%3}, {%4,%5,%6,%7}, {%8,%9}, {%0,%1,%2,%3};"
        : "+f"(c[0]), "+f"(c[1]), "+f"(c[2]), "+f"(c[3])
        : "r"(a[0]), "r"(a[1]), "r"(a[2]), "r"(a[3]), "r"(b[0]), "r"(b[1]));
}
static __device__ __forceinline__ void cpa16(uint32_t dst, const void* src) {
    asm volatile("cp.async.ca.shared.global [%0], [%1], 16;" :: "r"(dst), "l"(src));
}
static __device__ __forceinline__ uint32_t h2u(float a, float b) {
    __half2 h = __floats2half2_rn(a, b);
    return *(uint32_t*)&h;
}
#define DIV7(u) (((u) * 9363) >> 16)

static __device__ __forceinline__ float wsum(float v) {
    #pragma unroll
    for (int o = 16; o; o >>= 1) v += __shfl_xor_sync(0xffffffffu, v, o);
    return v;
}

// ---------------- fused weight conversion ----------------
__global__ void cvt_all(const float* __restrict__ qkvw, const float* __restrict__ projw,
                        const float* __restrict__ fc1w, const float* __restrict__ fc2w) {
    int i = blockIdx.x * 256 + threadIdx.x;
    const int S0 = 3 * Cc * Cc, S1 = Cc * Cc, S2 = HID * Cc, S3 = Cc * HID;
    if (i < S0) { g_qkvw16[i] = __float2half(qkvw[i]); return; }
    i -= S0;
    if (i < S1) { g_projw16[i] = __float2half(projw[i]); return; }
    i -= S1;
    if (i < S2) { g_fc1w16[i] = __float2half(fc1w[i]); return; }
    i -= S2;
    if (i < S3) { g_fc2w16[i] = __float2half(fc2w[i]); }
}

// ---------------- bias+mask tables: 4 window classes x 6 heads x 64x64 ----------------
__global__ void build_tab(const float* __restrict__ rpb) {
    int cls = blockIdx.x / NHd, nh = blockIdx.x - cls * NHd;
    int lastR = (cls >> 1) & 1, lastC = cls & 1;
    float* tp = g_tab + blockIdx.x * 4096;
    for (int idx = threadIdx.x; idx < 4096; idx += 256) {
        int rI = idx >> 6, m = idx & 63;
        float v;
        if (rI >= Nn) v = 0.0f;
        else if (m >= Nn) v = -1e30f;
        else {
            int r1 = DIV7(rI), c1 = rI - r1 * 7;
            int r2 = DIV7(m),  c2 = m  - r2 * 7;
            float bias = rpb[((r1 - r2 + 6) * 13 + (c1 - c2 + 6)) * NHd + nh];
            int rg1 = (lastR ? (r1 < 4 ? 1 : 2) : 0) * 3 + (lastC ? (c1 < 4 ? 1 : 2) : 0);
            int rg2 = (lastR ? (r2 < 4 ? 1 : 2) : 0) * 3 + (lastC ? (c2 < 4 ? 1 : 2) : 0);
            v = bias + ((rg1 == rg2) ? 0.0f : -100.0f);
        }
        tp[idx] = v;
    }
}

// ---------------- LN1 + roll(-3,-3) + window partition (warp per token) ----------------
__global__ void __launch_bounds__(256)
ln1_shift_part(const float* __restrict__ x, const float* __restrict__ g,
               const float* __restrict__ b) {
    int t = blockIdx.x * 8 + (threadIdx.x >> 5);
    int lane = threadIdx.x & 31;
    int wi = t / Nn, n = t - wi * Nn;
    int bi = wi >> 6, wl = wi & 63;
    int wr = wl >> 3, wc = wl & 7;
    int r = DIV7(n), c2 = n - r * 7;
    int hsrc = (wr * 7 + r + SS) % Hh;
    int wsrc = (wc * 7 + c2 + SS) % Ww;
    const float* row = x + ((size_t)bi * (Hh * Ww) + hsrc * Ww + wsrc) * Cc;
    float v[6];
    float s = 0.0f;
    #pragma unroll
    for (int j = 0; j < 6; j++) { v[j] = row[lane + 32 * j]; s += v[j]; }
    float mean = wsum(s) * (1.0f / Cc);
    float q = 0.0f;
    #pragma unroll
    for (int j = 0; j < 6; j++) { v[j] -= mean; q += v[j] * v[j]; }
    float inv = rsqrtf(wsum(q) * (1.0f / Cc) + 1e-5f);
    __half* o = g_xw16 + (size_t)t * Cc;
    #pragma unroll
    for (int j = 0; j < 6; j++) {
        int c = lane + 32 * j;
        o[c] = __float2half(v[j] * inv * g[c] + b[c]);
    }
}

// ---------------- LN2 (warp per token) ----------------
__global__ void __launch_bounds__(256)
ln2_k(const float* __restrict__ g, const float* __restrict__ b) {
    int t = blockIdx.x * 8 + (threadIdx.x >> 5);
    int lane = threadIdx.x & 31;
    const float* row = g_h + (size_t)t * Cc;
    float v[6];
    float s = 0.0f;
    #pragma unroll
    for (int j = 0; j < 6; j++) { v[j] = row[lane + 32 * j]; s += v[j]; }
    float mean = wsum(s) * (1.0f / Cc);
    float q = 0.0f;
    #pragma unroll
    for (int j = 0; j < 6; j++) { v[j] -= mean; q += v[j] * v[j]; }
    float inv = rsqrtf(wsum(q) * (1.0f / Cc) + 1e-5f);
    __half* o = g_ln216 + (size_t)t * Cc;
    #pragma unroll
    for (int j = 0; j < 6; j++) {
        int c = lane + 32 * j;
        o[c] = __float2half(v[j] * inv * g[c] + b[c]);
    }
}

// ---------------- wide fp16 TC GEMM: BM=128, BN=192, BK=32; 192 thr (6 warps 2x3) ----------------
// for qkv / fc1 (large grid, wide N).
// EPI: 0 = +bias, Q-cols(<192) scaled by SCALE -> fp16 (qkv)
//      1 = +bias, GELU -> fp16 (fc1)
#define A_STAGE 10240
#define B_STAGE 15360
#define GSMEM   (3 * (A_STAGE + B_STAGE))
template <int EPI>
__global__ void __launch_bounds__(192)
gemm_wide(const __half* __restrict__ A, const __half* __restrict__ Wt,
          const float* __restrict__ bias, __half* __restrict__ Cout, int Nc, int K) {
    extern __shared__ __align__(16) char smem[];
    const int tid  = threadIdx.x;
    const int wid  = tid >> 5, lane = tid & 31;
    const int gp   = lane >> 2, tg = lane & 3;
    const int m0   = blockIdx.y << 7;
    const int n0   = blockIdx.x * 192;
    const int wm   = (wid & 1) << 6;    // 0/64
    const int wn   = (wid >> 1) << 6;   // 0/64/128

    float acc[4][8][4];
    #pragma unroll
    for (int i = 0; i < 4; i++)
        #pragma unroll
        for (int j = 0; j < 8; j++)
            #pragma unroll
            for (int e = 0; e < 4; e++) acc[i][j][e] = 0.0f;

    const __half* Ap = A + (size_t)(m0 + tid) * K;         // valid for tid<128
    const __half* Wp = Wt + (size_t)(n0 + tid) * K;

    const uint32_t sA = smem_u32(smem);
    const uint32_t sB = sA + 3 * A_STAGE;
    const uint32_t aDst0 = sA + tid * 80;
    const uint32_t bDst0 = sB + tid * 80;

    const int aRow  = lane & 15;
    const int aCol8 = (lane >> 4) << 3;
    const int bRow  = ((lane & 16) >> 1) + (lane & 7);
    const int bCol8 = lane & 8;
    const uint32_t aOff = ((wm + aRow) * 40 + aCol8) << 1;
    const uint32_t bOff = ((wn + bRow) * 40 + bCol8) << 1;

    const int nc = K >> 5;

#define PREFETCH(ck, st) do {                                            \
        const __half* Ag_ = Ap + (ck) * 32;                              \
        const __half* Wg_ = Wp + (ck) * 32;                              \
        uint32_t aD_ = aDst0 + (st) * A_STAGE;                           \
        uint32_t bD_ = bDst0 + (st) * B_STAGE;                           \
        if (tid < 128) {                                                 \
            cpa16(aD_,      Ag_);      cpa16(aD_ + 16, Ag_ + 8);         \
            cpa16(aD_ + 32, Ag_ + 16); cpa16(aD_ + 48, Ag_ + 24);        \
        }                                                                \
        cpa16(bD_,      Wg_);      cpa16(bD_ + 16, Wg_ + 8);             \
        cpa16(bD_ + 32, Wg_ + 16); cpa16(bD_ + 48, Wg_ + 24);            \
        asm volatile("cp.async.commit_group;" ::: "memory");             \
    } while (0)

    PREFETCH(0, 0);
    PREFETCH(1, 1);

    for (int c = 0; c < nc; c++) {
        const int buf = c % 3;
        if (c + 1 < nc) asm volatile("cp.async.wait_group 1;" ::: "memory");
        else            asm volatile("cp.async.wait_group 0;" ::: "memory");
        __syncthreads();
        if (c + 2 < nc) PREFETCH(c + 2, (c + 2) % 3);

        const uint32_t aBase = sA + buf * A_STAGE + aOff;
        const uint32_t bBase = sB + buf * B_STAGE + bOff;
        #pragma unroll
        for (int kk = 0; kk < 2; kk++) {
            uint32_t af[4][4];
            #pragma unroll
            for (int i = 0; i < 4; i++)
                ldsm4(af[i][0], af[i][1], af[i][2], af[i][3],
                      aBase + ((i * 16 * 40 + kk * 16) << 1));
            uint32_t bf[16];
            #pragma unroll
            for (int j2 = 0; j2 < 4; j2++)
                ldsm4(bf[j2 * 4], bf[j2 * 4 + 1], bf[j2 * 4 + 2], bf[j2 * 4 + 3],
                      bBase + ((j2 * 16 * 40 + kk * 16) << 1));
            #pragma unroll
            for (int i = 0; i < 4; i++)
                #pragma unroll
                for (int j = 0; j < 8; j++)
                    mma_f16(acc[i][j], af[i], &bf[j * 2]);
        }
        __syncthreads();
    }
#undef PREFETCH

    #pragma unroll
    for (int i = 0; i < 4; i++) {
        #pragma unroll
        for (int half = 0; half < 2; half++) {
            const int row = m0 + wm + (i << 4) + gp + (half << 3);
            size_t rowoff = (size_t)row * Nc;
            #pragma unroll
            for (int j = 0; j < 8; j++) {
                const int ncol = n0 + wn + (j << 3) + (tg << 1);
                float v0 = acc[i][j][half * 2 + 0] + bias[ncol + 0];
                float v1 = acc[i][j][half * 2 + 1] + bias[ncol + 1];
                if (EPI == 0 && ncol < Cc) { v0 *= SCALE; v1 *= SCALE; }
                if (EPI == 1) {
                    v0 = 0.5f * v0 * (1.0f + erff(v0 * 0.70710678118654752f));
                    v1 = 0.5f * v1 * (1.0f + erff(v1 * 0.70710678118654752f));
                }
                *(__half2*)(Cout + rowoff + ncol) = __floats2half2_rn(v0, v1);
            }
        }
    }
}

// ---------------- BM=256, BN=64, BK=32; 256 thr (8 warps 4x2), 2-stage ----------------
// R8-measured best config for the Nc=192 GEMMs (proj, fc2).
// EPI: 2 = +bias, scatter window->token, +resid -> fp32 (proj)
//      3 = +bias, +resid -> fp32 (fc2)
template <int EPI>
__global__ void __launch_bounds__(256)
gemm_b256(const __half* __restrict__ A, const __half* __restrict__ Wt,
          const float* __restrict__ bias, const float* __restrict__ resid,
          float* __restrict__ Cout, int Nc, int K) {
    __shared__ __half As[2][256 * 40];
    __shared__ __half Bs[2][64 * 40];

    const int tid  = threadIdx.x;
    const int wid  = tid >> 5, lane = tid & 31;
    const int gp   = lane >> 2, tg = lane & 3;
    const int m0   = blockIdx.y << 8;
    const int n0   = blockIdx.x << 6;
    const int wm   = (wid & 3) << 6;    // 0/64/128/192
    const int wn   = (wid >> 2) << 5;   // 0/32

    float acc[4][4][4];
    #pragma unroll
    for (int i = 0; i < 4; i++)
        #pragma unroll
        for (int j = 0; j < 4; j++)
            #pragma unroll
            for (int e = 0; e < 4; e++) acc[i][j][e] = 0.0f;

    const __half* Ap = A + (size_t)(m0 + tid) * K;
    const int bRowL  = tid >> 2, bQ = tid & 3;
    const __half* Wp = Wt + (size_t)(n0 + bRowL) * K + bQ * 8;

    const uint32_t sA = smem_u32(As), sB = smem_u32(Bs);
    const uint32_t aDst0 = sA + tid * 80;
    const uint32_t bDst0 = sB + (bRowL * 40 + bQ * 8) * 2;

    const int aRow  = lane & 15;
    const int aCol8 = (lane >> 4) << 3;
    const int bRow  = ((lane & 16) >> 1) + (lane & 7);
    const int bCol8 = lane & 8;
    const uint32_t aOff = ((wm + aRow) * 40 + aCol8) << 1;
    const uint32_t bOff = ((wn + bRow) * 40 + bCol8) << 1;

    const int nc = K >> 5;

    #pragma unroll
    for (int s = 0; s < 4; s++) cpa16(aDst0 + s * 16, Ap + s * 8);
    cpa16(bDst0, Wp);
    asm volatile("cp.async.commit_group;" ::: "memory");

    for (int c = 0; c < nc; c++) {
        const int buf = c & 1;
        if (c + 1 < nc) {
            const int nb = (c + 1) & 1;
            const uint32_t aD = aDst0 + nb * (256 * 80);
            const uint32_t bD = bDst0 + nb * (64 * 80);
            const __half* Ag = Ap + (c + 1) * 32;
            const __half* Wg = Wp + (c + 1) * 32;
            #pragma unroll
            for (int s = 0; s < 4; s++) cpa16(aD + s * 16, Ag + s * 8);
            cpa16(bD, Wg);
            asm volatile("cp.async.commit_group;" ::: "memory");
            asm volatile("cp.async.wait_group 1;" ::: "memory");
        } else {
            asm volatile("cp.async.wait_group 0;" ::: "memory");
        }
        __syncthreads();

        const uint32_t aBase = sA + buf * (256 * 80) + aOff;
        const uint32_t bBase = sB + buf * (64 * 80) + bOff;
        #pragma unroll
        for (int kk = 0; kk < 2; kk++) {
            uint32_t af[4][4];
            #pragma unroll
            for (int i = 0; i < 4; i++)
                ldsm4(af[i][0], af[i][1], af[i][2], af[i][3],
                      aBase + ((i * 16 * 40 + kk * 16) << 1));
            uint32_t bf[4][2];
            ldsm4(bf[0][0], bf[0][1], bf[1][0], bf[1][1], bBase + ((kk * 16) << 1));
            ldsm4(bf[2][0], bf[2][1], bf[3][0], bf[3][1], bBase + ((16 * 40 + kk * 16) << 1));
            #pragma unroll
            for (int i = 0; i < 4; i++)
                #pragma unroll
                for (int j = 0; j < 4; j++)
                    mma_f16(acc[i][j], af[i], bf[j]);
        }
        __syncthreads();
    }

    #pragma unroll
    for (int i = 0; i < 4; i++) {
        #pragma unroll
        for (int half = 0; half < 2; half++) {
            const int row = m0 + wm + (i << 4) + gp + (half << 3);
            size_t rowoff;
            if (EPI == 2) {
                int wi2 = row / Nn, nn2 = row - wi2 * Nn;
                int bi = wi2 >> 6, wl = wi2 & 63;
                int wr = wl >> 3, wc = wl & 7;
                int rr = DIV7(nn2), cc = nn2 - rr * 7;
                int hd = (wr * 7 + rr + SS) % Hh;
                int wd = (wc * 7 + cc + SS) % Ww;
                rowoff = ((size_t)bi * (Hh * Ww) + hd * Ww + wd) * (size_t)Nc;
            } else {
                rowoff = (size_t)row * Nc;
            }
            #pragma unroll
            for (int j = 0; j < 4; j++) {
                const int ncol = n0 + wn + (j << 3) + (tg << 1);
                float v0 = acc[i][j][half * 2 + 0] + bias[ncol + 0] + resid[rowoff + ncol + 0];
                float v1 = acc[i][j][half * 2 + 1] + bias[ncol + 1] + resid[rowoff + ncol + 1];
                *(float2*)(Cout + rowoff + ncol) = make_float2(v0, v1);
            }
        }
    }
}

// ---------------- tensor-core window attention: block = (window, head), 128 thr ----------------
__global__ void __launch_bounds__(128)
attn_k() {
    __shared__ __half Qs[64 * 40];
    __shared__ __half Ks[64 * 40];
    __shared__ __half Vt[32 * 72];

    const int wi = blockIdx.x;
    const int nh = blockIdx.y;
    const int tid = threadIdx.x;
    const int wid = tid >> 5, lane = tid & 31;
    const int gp = lane >> 2, tg = lane & 3;

    const int wl = wi & 63;
    const int cls = (((wl >> 3) == 7) ? 2 : 0) | (((wl & 7) == 7) ? 1 : 0);
    const float* tp = g_tab + (cls * NHd + nh) * 4096;

    for (int idx = tid; idx < 64 * 4; idx += 128) {
        int row = idx >> 2, seg = idx & 3;
        uint4 zq = make_uint4(0, 0, 0, 0), zk = zq;
        if (row < Nn) {
            const __half* base = g_qkv16 + (size_t)(wi * Nn + row) * (3 * Cc) + nh * HD + seg * 8;
            zq = *(const uint4*)(base);
            zk = *(const uint4*)(base + Cc);
        }
        *(uint4*)(Qs + row * 40 + seg * 8) = zq;
        *(uint4*)(Ks + row * 40 + seg * 8) = zk;
    }
    for (int idx = tid; idx < 64 * 16; idx += 128) {
        int row = idx >> 4, p = idx & 15;
        __half2 v = __float2half2_rn(0.0f);
        if (row < Nn)
            v = *(const __half2*)(g_qkv16 + (size_t)(wi * Nn + row) * (3 * Cc) + 2 * Cc + nh * HD + 2 * p);
        Vt[(2 * p) * 72 + row]     = __low2half(v);
        Vt[(2 * p + 1) * 72 + row] = __high2half(v);
    }

    const int rowL = wid * 16 + gp, rowH = rowL + 8;
    float st[8][4];
    #pragma unroll
    for (int j = 0; j < 8; j++) {
        float2 vL = *(const float2*)(tp + rowL * 64 + j * 8 + tg * 2);
        float2 vH = *(const float2*)(tp + rowH * 64 + j * 8 + tg * 2);
        st[j][0] = vL.x; st[j][1] = vL.y;
        st[j][2] = vH.x; st[j][3] = vH.y;
    }
    __syncthreads();

    const int aRow  = lane & 15;
    const int aCol8 = (lane >> 4) << 3;
    const int bRow  = ((lane & 16) >> 1) + (lane & 7);
    const int bCol8 = lane & 8;
    const uint32_t qBase = smem_u32(Qs) + (((wid * 16 + aRow) * 40 + aCol8) << 1);
    const uint32_t kBase = smem_u32(Ks) + ((bRow * 40 + bCol8) << 1);

    #pragma unroll
    for (int kk = 0; kk < 2; kk++) {
        uint32_t af[4];
        ldsm4(af[0], af[1], af[2], af[3], qBase + (kk * 16 << 1));
        #pragma unroll
        for (int j2 = 0; j2 < 4; j2++) {
            uint32_t bf[2][2];
            ldsm4(bf[0][0], bf[0][1], bf[1][0], bf[1][1],
                  kBase + ((j2 * 16 * 40 + kk * 16) << 1));
            mma_f16(st[2 * j2],     af, bf[0]);
            mma_f16(st[2 * j2 + 1], af, bf[1]);
        }
    }

    #pragma unroll
    for (int hrow = 0; hrow < 2; hrow++) {
        float mx = -1e30f;
        #pragma unroll
        for (int j = 0; j < 8; j++) {
            mx = fmaxf(mx, st[j][hrow * 2]);
            mx = fmaxf(mx, st[j][hrow * 2 + 1]);
        }
        mx = fmaxf(mx, __shfl_xor_sync(0xffffffffu, mx, 1));
        mx = fmaxf(mx, __shfl_xor_sync(0xffffffffu, mx, 2));
        float sm = 0.0f;
        #pragma unroll
        for (int j = 0; j < 8; j++) {
            #pragma unroll
            for (int e = 0; e < 2; e++) {
                float ev = __expf(st[j][hrow * 2 + e] - mx);
                st[j][hrow * 2 + e] = ev;
                sm += ev;
            }
        }
        sm += __shfl_xor_sync(0xffffffffu, sm, 1);
        sm += __shfl_xor_sync(0xffffffffu, sm, 2);
        float inv = 1.0f / sm;
        #pragma unroll
        for (int j = 0; j < 8; j++) {
            st[j][hrow * 2] *= inv;
            st[j][hrow * 2 + 1] *= inv;
        }
    }

    float o[4][4];
    #pragma unroll
    for (int jt = 0; jt < 4; jt++)
        #pragma unroll
        for (int e = 0; e < 4; e++) o[jt][e] = 0.0f;

    const uint32_t vBase = smem_u32(Vt) + ((bRow * 72 + bCol8) << 1);
    #pragma unroll
    for (int kk = 0; kk < 4; kk++) {
        uint32_t a[4];
        a[0] = h2u(st[2 * kk][0],     st[2 * kk][1]);
        a[1] = h2u(st[2 * kk][2],     st[2 * kk][3]);
        a[2] = h2u(st[2 * kk + 1][0], st[2 * kk + 1][1]);
        a[3] = h2u(st[2 * kk + 1][2], st[2 * kk + 1][3]);
        #pragma unroll
        for (int jj2 = 0; jj2 < 2; jj2++) {
            uint32_t bf[2][2];
            ldsm4(bf[0][0], bf[0][1], bf[1][0], bf[1][1],
                  vBase + ((jj2 * 16 * 72 + kk * 16) << 1));
            mma_f16(o[2 * jj2],     a, bf[0]);
            mma_f16(o[2 * jj2 + 1], a, bf[1]);
        }
    }

    __half* outp = g_attn16 + (size_t)wi * Nn * Cc + nh * HD;
    #pragma unroll
    for (int hrow = 0; hrow < 2; hrow++) {
        const int rI = hrow ? rowH : rowL;
        if (rI < Nn) {
            __half* rp = outp + (size_t)rI * Cc;
            #pragma unroll
            for (int jt = 0; jt < 4; jt++)
                *(__half2*)(rp + jt * 8 + tg * 2) =
                    __floats2half2_rn(o[jt][hrow * 2], o[jt][hrow * 2 + 1]);
        }
    }
}

// ---------------- host ----------------
extern "C" void kernel_launch(void* const* d_in, const int* in_sizes, int n_in,
                              void* d_out, int out_size) {
    const float* x     = (const float*)d_in[0];
    const float* n1g   = (const float*)d_in[1];
    const float* n1b   = (const float*)d_in[2];
    const float* qkvw  = (const float*)d_in[3];
    const float* qkvb  = (const float*)d_in[4];
    const float* projw = (const float*)d_in[5];
    const float* projb = (const float*)d_in[6];
    const float* rpb   = (const float*)d_in[7];
    const float* n2g   = (const float*)d_in[8];
    const float* n2b   = (const float*)d_in[9];
    const float* fc1w  = (const float*)d_in[10];
    const float* fc1b  = (const float*)d_in[11];
    const float* fc2w  = (const float*)d_in[12];
    const float* fc2b  = (const float*)d_in[13];
    float* out = (float*)d_out;

    static __half *p_xw16 = nullptr, *p_qkv16, *p_attn16, *p_ln216, *p_act16,
                  *p_qkvw16, *p_projw16, *p_fc1w16, *p_fc2w16;
    static float *p_h;
    if (!p_xw16) {
        cudaGetSymbolAddress((void**)&p_xw16,   g_xw16);
        cudaGetSymbolAddress((void**)&p_qkv16,  g_qkv16);
        cudaGetSymbolAddress((void**)&p_attn16, g_attn16);
        cudaGetSymbolAddress((void**)&p_h,      g_h);
        cudaGetSymbolAddress((void**)&p_ln216,  g_ln216);
        cudaGetSymbolAddress((void**)&p_act16,  g_act16);
        cudaGetSymbolAddress((void**)&p_qkvw16, g_qkvw16);
        cudaGetSymbolAddress((void**)&p_projw16,g_projw16);
        cudaGetSymbolAddress((void**)&p_fc1w16, g_fc1w16);
        cudaGetSymbolAddress((void**)&p_fc2w16, g_fc2w16);
        cudaFuncSetAttribute(gemm_wide<0>, cudaFuncAttributeMaxDynamicSharedMemorySize, GSMEM);
        cudaFuncSetAttribute(gemm_wide<1>, cudaFuncAttributeMaxDynamicSharedMemorySize, GSMEM);
    }

    // 0) weight conversion + bias/mask tables
    const int CV = 3 * Cc * Cc + Cc * Cc + HID * Cc + Cc * HID;
    cvt_all<<<(CV + 255) / 256, 256>>>(qkvw, projw, fc1w, fc2w);
    build_tab<<<24, 256>>>(rpb);

    // 1) LN1 + roll + window partition -> fp16
    ln1_shift_part<<<TOK / 8, 256>>>(x, n1g, n1b);
    // 2) QKV GEMM (wide; Q prescaled by SCALE in epilogue)
    gemm_wide<0><<<dim3(3, TOK / 128), 192, GSMEM>>>(p_xw16, p_qkvw16, qkvb, p_qkv16, 3 * Cc, Cc);
    // 3) window attention
    attn_k<<<dim3(NWTOT, NHd), 128>>>();
    // 4) proj GEMM + scatter + residual -> h (R8 config)
    gemm_b256<2><<<dim3(3, TOK / 256), 256>>>(p_attn16, p_projw16, projb, x, p_h, Cc, Cc);
    // 5) LN2 -> fp16
    ln2_k<<<TOK / 8, 256>>>(n2g, n2b);
    // 6) FC1 + GELU -> fp16 (wide)
    gemm_wide<1><<<dim3(4, TOK / 128), 192, GSMEM>>>(p_ln216, p_fc1w16, fc1b, p_act16, HID, Cc);
    // 7) FC2 + residual -> out (R8 config)
    gemm_b256<3><<<dim3(3, TOK / 256), 256>>>(p_act16, p_fc2w16, fc2b, p_h, out, Cc, HID);
}

// round 13
// speedup vs baseline: 1.0780x; 1.0491x over previous
#include <cuda_runtime.h>
#include <cuda_fp16.h>
#include <math.h>
#include <stddef.h>
#include <stdint.h>

#define Bb   32
#define Hh   56
#define Ww   56
#define Cc   192
#define WS   7
#define SS   3
#define NHd  6
#define Nn   49
#define HD   32
#define NWTOT 2048
#define TOK  100352
#define HID  768
#define SCALE 0.17677669529663687f  /* 32^-0.5 */

// ---------------- scratch (device globals; no allocations) ----------------
__device__ __half g_xw16  [(size_t)TOK * Cc];
__device__ __half g_qkv16 [(size_t)TOK * 3 * Cc];
__device__ __half g_attn16[(size_t)TOK * Cc];
__device__ float  g_h     [(size_t)TOK * Cc];
__device__ __half g_ln216 [(size_t)TOK * Cc];
__device__ __half g_act16 [(size_t)TOK * HID];
__device__ __half g_qkvw16[3 * Cc * Cc];
__device__ __half g_projw16[Cc * Cc];
__device__ __half g_fc1w16[HID * Cc];
__device__ __half g_fc2w16[Cc * HID];
__device__ float  g_tab   [24 * 64 * 64];     // (cls*6+nh) x 64 x 64 bias+mask

// ---------------- helpers ----------------
static __device__ __forceinline__ uint32_t smem_u32(const void* p) {
    uint32_t a;
    asm("{ .reg .u64 t; cvta.to.shared.u64 t, %1; cvt.u32.u64 %0, t; }" : "=r"(a) : "l"(p));
    return a;
}
static __device__ __forceinline__ void ldsm4(uint32_t& r0, uint32_t& r1, uint32_t& r2,
                                             uint32_t& r3, uint32_t addr) {
    asm volatile("ldmatrix.sync.aligned.m8n8.x4.shared.b16 {%0,%1,%2,%3}, [%4];"
                 : "=r"(r0), "=r"(r1), "=r"(r2), "=r"(r3) : "r"(addr));
}
static __device__ __forceinline__ void mma_f16(float* c, const uint32_t* a, const uint32_t* b) {
    asm volatile(
        "mma.sync.aligned.m16n8k16.row.col.f32.f16.f16.f32 "
        "{%0,%1,%2,%3}, {%4,%5,%6,%7}, {%8,%9}, {%0,%1,%2,%3};"
        : "+f"(c[0]), "+f"(c[1]), "+f"(c[2]), "+f"(c[3])
        : "r"(a[0]), "r"(a[1]), "r"(a[2]), "r"(a[3]), "r"(b[0]), "r"(b[1]));
}
static __device__ __forceinline__ void cpa16(uint32_t dst, const void* src) {
    asm volatile("cp.async.ca.shared.global [%0], [%1], 16;" :: "r"(dst), "l"(src));
}
static __device__ __forceinline__ uint32_t h2u(float a, float b) {
    __half2 h = __floats2half2_rn(a, b);
    return *(uint32_t*)&h;
}
#define DIV7(u) (((u) * 9363) >> 16)

static __device__ __forceinline__ float wsum(float v) {
    #pragma unroll
    for (int o = 16; o; o >>= 1) v += __shfl_xor_sync(0xffffffffu, v, o);
    return v;
}

// ---------------- fused weight conversion ----------------
__global__ void cvt_all(const float* __restrict__ qkvw, const float* __restrict__ projw,
                        const float* __restrict__ fc1w, const float* __restrict__ fc2w) {
    int i = blockIdx.x * 256 + threadIdx.x;
    const int S0 = 3 * Cc * Cc, S1 = Cc * Cc, S2 = HID * Cc, S3 = Cc * HID;
    if (i < S0) { g_qkvw16[i] = __float2half(qkvw[i]); return; }
    i -= S0;
    if (i < S1) { g_projw16[i] = __float2half(projw[i]); return; }
    i -= S1;
    if (i < S2) { g_fc1w16[i] = __float2half(fc1w[i]); return; }
    i -= S2;
    if (i < S3) { g_fc2w16[i] = __float2half(fc2w[i]); }
}

// ---------------- bias+mask tables: 4 window classes x 6 heads x 64x64 ----------------
__global__ void build_tab(const float* __restrict__ rpb) {
    int cls = blockIdx.x / NHd, nh = blockIdx.x - cls * NHd;
    int lastR = (cls >> 1) & 1, lastC = cls & 1;
    float* tp = g_tab + blockIdx.x * 4096;
    for (int idx = threadIdx.x; idx < 4096; idx += 256) {
        int rI = idx >> 6, m = idx & 63;
        float v;
        if (rI >= Nn) v = 0.0f;
        else if (m >= Nn) v = -1e30f;
        else {
            int r1 = DIV7(rI), c1 = rI - r1 * 7;
            int r2 = DIV7(m),  c2 = m  - r2 * 7;
            float bias = rpb[((r1 - r2 + 6) * 13 + (c1 - c2 + 6)) * NHd + nh];
            int rg1 = (lastR ? (r1 < 4 ? 1 : 2) : 0) * 3 + (lastC ? (c1 < 4 ? 1 : 2) : 0);
            int rg2 = (lastR ? (r2 < 4 ? 1 : 2) : 0) * 3 + (lastC ? (c2 < 4 ? 1 : 2) : 0);
            v = bias + ((rg1 == rg2) ? 0.0f : -100.0f);
        }
        tp[idx] = v;
    }
}

// ---------------- LN1 + roll(-3,-3) + window partition (warp per token) ----------------
__global__ void __launch_bounds__(256)
ln1_shift_part(const float* __restrict__ x, const float* __restrict__ g,
               const float* __restrict__ b) {
    int t = blockIdx.x * 8 + (threadIdx.x >> 5);
    int lane = threadIdx.x & 31;
    int wi = t / Nn, n = t - wi * Nn;
    int bi = wi >> 6, wl = wi & 63;
    int wr = wl >> 3, wc = wl & 7;
    int r = DIV7(n), c2 = n - r * 7;
    int hsrc = (wr * 7 + r + SS) % Hh;
    int wsrc = (wc * 7 + c2 + SS) % Ww;
    const float* row = x + ((size_t)bi * (Hh * Ww) + hsrc * Ww + wsrc) * Cc;
    float v[6];
    float s = 0.0f;
    #pragma unroll
    for (int j = 0; j < 6; j++) { v[j] = row[lane + 32 * j]; s += v[j]; }
    float mean = wsum(s) * (1.0f / Cc);
    float q = 0.0f;
    #pragma unroll
    for (int j = 0; j < 6; j++) { v[j] -= mean; q += v[j] * v[j]; }
    float inv = rsqrtf(wsum(q) * (1.0f / Cc) + 1e-5f);
    __half* o = g_xw16 + (size_t)t * Cc;
    #pragma unroll
    for (int j = 0; j < 6; j++) {
        int c = lane + 32 * j;
        o[c] = __float2half(v[j] * inv * g[c] + b[c]);
    }
}

// ---------------- LN2 (warp per token) ----------------
__global__ void __launch_bounds__(256)
ln2_k(const float* __restrict__ g, const float* __restrict__ b) {
    int t = blockIdx.x * 8 + (threadIdx.x >> 5);
    int lane = threadIdx.x & 31;
    const float* row = g_h + (size_t)t * Cc;
    float v[6];
    float s = 0.0f;
    #pragma unroll
    for (int j = 0; j < 6; j++) { v[j] = row[lane + 32 * j]; s += v[j]; }
    float mean = wsum(s) * (1.0f / Cc);
    float q = 0.0f;
    #pragma unroll
    for (int j = 0; j < 6; j++) { v[j] -= mean; q += v[j] * v[j]; }
    float inv = rsqrtf(wsum(q) * (1.0f / Cc) + 1e-5f);
    __half* o = g_ln216 + (size_t)t * Cc;
    #pragma unroll
    for (int j = 0; j < 6; j++) {
        int c = lane + 32 * j;
        o[c] = __float2half(v[j] * inv * g[c] + b[c]);
    }
}

// ---------------- wide fp16 TC GEMM: BM=128, BN=192, BK=32; 192 thr (6 warps 2x3) ----------------
// qkv ONLY (grid 2352 = 8 perfect waves at 2 CTA/SM).
// EPI 0: +bias, Q-cols(<192) scaled by SCALE -> fp16
#define A_STAGE 10240
#define B_STAGE 15360
#define GSMEM   (3 * (A_STAGE + B_STAGE))
__global__ void __launch_bounds__(192)
gemm_wide(const __half* __restrict__ A, const __half* __restrict__ Wt,
          const float* __restrict__ bias, __half* __restrict__ Cout, int Nc, int K) {
    extern __shared__ __align__(16) char smem[];
    const int tid  = threadIdx.x;
    const int wid  = tid >> 5, lane = tid & 31;
    const int gp   = lane >> 2, tg = lane & 3;
    const int m0   = blockIdx.y << 7;
    const int n0   = blockIdx.x * 192;
    const int wm   = (wid & 1) << 6;    // 0/64
    const int wn   = (wid >> 1) << 6;   // 0/64/128

    float acc[4][8][4];
    #pragma unroll
    for (int i = 0; i < 4; i++)
        #pragma unroll
        for (int j = 0; j < 8; j++)
            #pragma unroll
            for (int e = 0; e < 4; e++) acc[i][j][e] = 0.0f;

    const __half* Ap = A + (size_t)(m0 + tid) * K;         // valid for tid<128
    const __half* Wp = Wt + (size_t)(n0 + tid) * K;

    const uint32_t sA = smem_u32(smem);
    const uint32_t sB = sA + 3 * A_STAGE;
    const uint32_t aDst0 = sA + tid * 80;
    const uint32_t bDst0 = sB + tid * 80;

    const int aRow  = lane & 15;
    const int aCol8 = (lane >> 4) << 3;
    const int bRow  = ((lane & 16) >> 1) + (lane & 7);
    const int bCol8 = lane & 8;
    const uint32_t aOff = ((wm + aRow) * 40 + aCol8) << 1;
    const uint32_t bOff = ((wn + bRow) * 40 + bCol8) << 1;

    const int nc = K >> 5;

#define PREFETCH(ck, st) do {                                            \
        const __half* Ag_ = Ap + (ck) * 32;                              \
        const __half* Wg_ = Wp + (ck) * 32;                              \
        uint32_t aD_ = aDst0 + (st) * A_STAGE;                           \
        uint32_t bD_ = bDst0 + (st) * B_STAGE;                           \
        if (tid < 128) {                                                 \
            cpa16(aD_,      Ag_);      cpa16(aD_ + 16, Ag_ + 8);         \
            cpa16(aD_ + 32, Ag_ + 16); cpa16(aD_ + 48, Ag_ + 24);        \
        }                                                                \
        cpa16(bD_,      Wg_);      cpa16(bD_ + 16, Wg_ + 8);             \
        cpa16(bD_ + 32, Wg_ + 16); cpa16(bD_ + 48, Wg_ + 24);            \
        asm volatile("cp.async.commit_group;" ::: "memory");             \
    } while (0)

    PREFETCH(0, 0);
    PREFETCH(1, 1);

    for (int c = 0; c < nc; c++) {
        const int buf = c % 3;
        if (c + 1 < nc) asm volatile("cp.async.wait_group 1;" ::: "memory");
        else            asm volatile("cp.async.wait_group 0;" ::: "memory");
        __syncthreads();
        if (c + 2 < nc) PREFETCH(c + 2, (c + 2) % 3);

        const uint32_t aBase = sA + buf * A_STAGE + aOff;
        const uint32_t bBase = sB + buf * B_STAGE + bOff;
        #pragma unroll
        for (int kk = 0; kk < 2; kk++) {
            uint32_t af[4][4];
            #pragma unroll
            for (int i = 0; i < 4; i++)
                ldsm4(af[i][0], af[i][1], af[i][2], af[i][3],
                      aBase + ((i * 16 * 40 + kk * 16) << 1));
            uint32_t bf[16];
            #pragma unroll
            for (int j2 = 0; j2 < 4; j2++)
                ldsm4(bf[j2 * 4], bf[j2 * 4 + 1], bf[j2 * 4 + 2], bf[j2 * 4 + 3],
                      bBase + ((j2 * 16 * 40 + kk * 16) << 1));
            #pragma unroll
            for (int i = 0; i < 4; i++)
                #pragma unroll
                for (int j = 0; j < 8; j++)
                    mma_f16(acc[i][j], af[i], &bf[j * 2]);
        }
        __syncthreads();
    }
#undef PREFETCH

    #pragma unroll
    for (int i = 0; i < 4; i++) {
        #pragma unroll
        for (int half = 0; half < 2; half++) {
            const int row = m0 + wm + (i << 4) + gp + (half << 3);
            size_t rowoff = (size_t)row * Nc;
            #pragma unroll
            for (int j = 0; j < 8; j++) {
                const int ncol = n0 + wn + (j << 3) + (tg << 1);
                float v0 = acc[i][j][half * 2 + 0] + bias[ncol + 0];
                float v1 = acc[i][j][half * 2 + 1] + bias[ncol + 1];
                if (ncol < Cc) { v0 *= SCALE; v1 *= SCALE; }
                *(__half2*)(Cout + rowoff + ncol) = __floats2half2_rn(v0, v1);
            }
        }
    }
}

// ---------------- BM=256, BN=64, BK=32; 256 thr (8 warps 4x2), 2-stage (R8 config) ----------------
// EPI: 1 = +bias, GELU -> fp16 (fc1)
//      2 = +bias, scatter window->token, +resid -> fp32 (proj)
//      3 = +bias, +resid -> fp32 (fc2)
template <int EPI>
__global__ void __launch_bounds__(256)
gemm_b256(const __half* __restrict__ A, const __half* __restrict__ Wt,
          const float* __restrict__ bias, const float* __restrict__ resid,
          void* __restrict__ Cout, int Nc, int K) {
    __shared__ __half As[2][256 * 40];
    __shared__ __half Bs[2][64 * 40];

    const int tid  = threadIdx.x;
    const int wid  = tid >> 5, lane = tid & 31;
    const int gp   = lane >> 2, tg = lane & 3;
    const int m0   = blockIdx.y << 8;
    const int n0   = blockIdx.x << 6;
    const int wm   = (wid & 3) << 6;    // 0/64/128/192
    const int wn   = (wid >> 2) << 5;   // 0/32

    float acc[4][4][4];
    #pragma unroll
    for (int i = 0; i < 4; i++)
        #pragma unroll
        for (int j = 0; j < 4; j++)
            #pragma unroll
            for (int e = 0; e < 4; e++) acc[i][j][e] = 0.0f;

    const __half* Ap = A + (size_t)(m0 + tid) * K;
    const int bRowL  = tid >> 2, bQ = tid & 3;
    const __half* Wp = Wt + (size_t)(n0 + bRowL) * K + bQ * 8;

    const uint32_t sA = smem_u32(As), sB = smem_u32(Bs);
    const uint32_t aDst0 = sA + tid * 80;
    const uint32_t bDst0 = sB + (bRowL * 40 + bQ * 8) * 2;

    const int aRow  = lane & 15;
    const int aCol8 = (lane >> 4) << 3;
    const int bRow  = ((lane & 16) >> 1) + (lane & 7);
    const int bCol8 = lane & 8;
    const uint32_t aOff = ((wm + aRow) * 40 + aCol8) << 1;
    const uint32_t bOff = ((wn + bRow) * 40 + bCol8) << 1;

    const int nc = K >> 5;

    #pragma unroll
    for (int s = 0; s < 4; s++) cpa16(aDst0 + s * 16, Ap + s * 8);
    cpa16(bDst0, Wp);
    asm volatile("cp.async.commit_group;" ::: "memory");

    for (int c = 0; c < nc; c++) {
        const int buf = c & 1;
        if (c + 1 < nc) {
            const int nb = (c + 1) & 1;
            const uint32_t aD = aDst0 + nb * (256 * 80);
            const uint32_t bD = bDst0 + nb * (64 * 80);
            const __half* Ag = Ap + (c + 1) * 32;
            const __half* Wg = Wp + (c + 1) * 32;
            #pragma unroll
            for (int s = 0; s < 4; s++) cpa16(aD + s * 16, Ag + s * 8);
            cpa16(bD, Wg);
            asm volatile("cp.async.commit_group;" ::: "memory");
            asm volatile("cp.async.wait_group 1;" ::: "memory");
        } else {
            asm volatile("cp.async.wait_group 0;" ::: "memory");
        }
        __syncthreads();

        const uint32_t aBase = sA + buf * (256 * 80) + aOff;
        const uint32_t bBase = sB + buf * (64 * 80) + bOff;
        #pragma unroll
        for (int kk = 0; kk < 2; kk++) {
            uint32_t af[4][4];
            #pragma unroll
            for (int i = 0; i < 4; i++)
                ldsm4(af[i][0], af[i][1], af[i][2], af[i][3],
                      aBase + ((i * 16 * 40 + kk * 16) << 1));
            uint32_t bf[4][2];
            ldsm4(bf[0][0], bf[0][1], bf[1][0], bf[1][1], bBase + ((kk * 16) << 1));
            ldsm4(bf[2][0], bf[2][1], bf[3][0], bf[3][1], bBase + ((16 * 40 + kk * 16) << 1));
            #pragma unroll
            for (int i = 0; i < 4; i++)
                #pragma unroll
                for (int j = 0; j < 4; j++)
                    mma_f16(acc[i][j], af[i], bf[j]);
        }
        __syncthreads();
    }

    #pragma unroll
    for (int i = 0; i < 4; i++) {
        #pragma unroll
        for (int half = 0; half < 2; half++) {
            const int row = m0 + wm + (i << 4) + gp + (half << 3);
            size_t rowoff;
            if (EPI == 2) {
                int wi2 = row / Nn, nn2 = row - wi2 * Nn;
                int bi = wi2 >> 6, wl = wi2 & 63;
                int wr = wl >> 3, wc = wl & 7;
                int rr = DIV7(nn2), cc = nn2 - rr * 7;
                int hd = (wr * 7 + rr + SS) % Hh;
                int wd = (wc * 7 + cc + SS) % Ww;
                rowoff = ((size_t)bi * (Hh * Ww) + hd * Ww + wd) * (size_t)Nc;
            } else {
                rowoff = (size_t)row * Nc;
            }
            #pragma unroll
            for (int j = 0; j < 4; j++) {
                const int ncol = n0 + wn + (j << 3) + (tg << 1);
                float v0 = acc[i][j][half * 2 + 0] + bias[ncol + 0];
                float v1 = acc[i][j][half * 2 + 1] + bias[ncol + 1];
                if (EPI == 1) {
                    v0 = 0.5f * v0 * (1.0f + erff(v0 * 0.70710678118654752f));
                    v1 = 0.5f * v1 * (1.0f + erff(v1 * 0.70710678118654752f));
                    *(__half2*)((__half*)Cout + rowoff + ncol) = __floats2half2_rn(v0, v1);
                } else {
                    v0 += resid[rowoff + ncol + 0];
                    v1 += resid[rowoff + ncol + 1];
                    *(float2*)((float*)Cout + rowoff + ncol) = make_float2(v0, v1);
                }
            }
        }
    }
}

// ---------------- tensor-core window attention: block = (window, head), 128 thr ----------------
__global__ void __launch_bounds__(128)
attn_k() {
    __shared__ __half Qs[64 * 40];
    __shared__ __half Ks[64 * 40];
    __shared__ __half Vt[32 * 72];

    const int wi = blockIdx.x;
    const int nh = blockIdx.y;
    const int tid = threadIdx.x;
    const int wid = tid >> 5, lane = tid & 31;
    const int gp = lane >> 2, tg = lane & 3;

    const int wl = wi & 63;
    const int cls = (((wl >> 3) == 7) ? 2 : 0) | (((wl & 7) == 7) ? 1 : 0);
    const float* tp = g_tab + (cls * NHd + nh) * 4096;

    for (int idx = tid; idx < 64 * 4; idx += 128) {
        int row = idx >> 2, seg = idx & 3;
        uint4 zq = make_uint4(0, 0, 0, 0), zk = zq;
        if (row < Nn) {
            const __half* base = g_qkv16 + (size_t)(wi * Nn + row) * (3 * Cc) + nh * HD + seg * 8;
            zq = *(const uint4*)(base);
            zk = *(const uint4*)(base + Cc);
        }
        *(uint4*)(Qs + row * 40 + seg * 8) = zq;
        *(uint4*)(Ks + row * 40 + seg * 8) = zk;
    }
    for (int idx = tid; idx < 64 * 16; idx += 128) {
        int row = idx >> 4, p = idx & 15;
        __half2 v = __float2half2_rn(0.0f);
        if (row < Nn)
            v = *(const __half2*)(g_qkv16 + (size_t)(wi * Nn + row) * (3 * Cc) + 2 * Cc + nh * HD + 2 * p);
        Vt[(2 * p) * 72 + row]     = __low2half(v);
        Vt[(2 * p + 1) * 72 + row] = __high2half(v);
    }

    const int rowL = wid * 16 + gp, rowH = rowL + 8;
    float st[8][4];
    #pragma unroll
    for (int j = 0; j < 8; j++) {
        float2 vL = *(const float2*)(tp + rowL * 64 + j * 8 + tg * 2);
        float2 vH = *(const float2*)(tp + rowH * 64 + j * 8 + tg * 2);
        st[j][0] = vL.x; st[j][1] = vL.y;
        st[j][2] = vH.x; st[j][3] = vH.y;
    }
    __syncthreads();

    const int aRow  = lane & 15;
    const int aCol8 = (lane >> 4) << 3;
    const int bRow  = ((lane & 16) >> 1) + (lane & 7);
    const int bCol8 = lane & 8;
    const uint32_t qBase = smem_u32(Qs) + (((wid * 16 + aRow) * 40 + aCol8) << 1);
    const uint32_t kBase = smem_u32(Ks) + ((bRow * 40 + bCol8) << 1);

    #pragma unroll
    for (int kk = 0; kk < 2; kk++) {
        uint32_t af[4];
        ldsm4(af[0], af[1], af[2], af[3], qBase + (kk * 16 << 1));
        #pragma unroll
        for (int j2 = 0; j2 < 4; j2++) {
            uint32_t bf[2][2];
            ldsm4(bf[0][0], bf[0][1], bf[1][0], bf[1][1],
                  kBase + ((j2 * 16 * 40 + kk * 16) << 1));
            mma_f16(st[2 * j2],     af, bf[0]);
            mma_f16(st[2 * j2 + 1], af, bf[1]);
        }
    }

    #pragma unroll
    for (int hrow = 0; hrow < 2; hrow++) {
        float mx = -1e30f;
        #pragma unroll
        for (int j = 0; j < 8; j++) {
            mx = fmaxf(mx, st[j][hrow * 2]);
            mx = fmaxf(mx, st[j][hrow * 2 + 1]);
        }
        mx = fmaxf(mx, __shfl_xor_sync(0xffffffffu, mx, 1));
        mx = fmaxf(mx, __shfl_xor_sync(0xffffffffu, mx, 2));
        float sm = 0.0f;
        #pragma unroll
        for (int j = 0; j < 8; j++) {
            #pragma unroll
            for (int e = 0; e < 2; e++) {
                float ev = __expf(st[j][hrow * 2 + e] - mx);
                st[j][hrow * 2 + e] = ev;
                sm += ev;
            }
        }
        sm += __shfl_xor_sync(0xffffffffu, sm, 1);
        sm += __shfl_xor_sync(0xffffffffu, sm, 2);
        float inv = 1.0f / sm;
        #pragma unroll
        for (int j = 0; j < 8; j++) {
            st[j][hrow * 2] *= inv;
            st[j][hrow * 2 + 1] *= inv;
        }
    }

    float o[4][4];
    #pragma unroll
    for (int jt = 0; jt < 4; jt++)
        #pragma unroll
        for (int e = 0; e < 4; e++) o[jt][e] = 0.0f;

    const uint32_t vBase = smem_u32(Vt) + ((bRow * 72 + bCol8) << 1);
    #pragma unroll
    for (int kk = 0; kk < 4; kk++) {
        uint32_t a[4];
        a[0] = h2u(st[2 * kk][0],     st[2 * kk][1]);
        a[1] = h2u(st[2 * kk][2],     st[2 * kk][3]);
        a[2] = h2u(st[2 * kk + 1][0], st[2 * kk + 1][1]);
        a[3] = h2u(st[2 * kk + 1][2], st[2 * kk + 1][3]);
        #pragma unroll
        for (int jj2 = 0; jj2 < 2; jj2++) {
            uint32_t bf[2][2];
            ldsm4(bf[0][0], bf[0][1], bf[1][0], bf[1][1],
                  vBase + ((jj2 * 16 * 72 + kk * 16) << 1));
            mma_f16(o[2 * jj2],     a, bf[0]);
            mma_f16(o[2 * jj2 + 1], a, bf[1]);
        }
    }

    __half* outp = g_attn16 + (size_t)wi * Nn * Cc + nh * HD;
    #pragma unroll
    for (int hrow = 0; hrow < 2; hrow++) {
        const int rI = hrow ? rowH : rowL;
        if (rI < Nn) {
            __half* rp = outp + (size_t)rI * Cc;
            #pragma unroll
            for (int jt = 0; jt < 4; jt++)
                *(__half2*)(rp + jt * 8 + tg * 2) =
                    __floats2half2_rn(o[jt][hrow * 2], o[jt][hrow * 2 + 1]);
        }
    }
}

// ---------------- host ----------------
extern "C" void kernel_launch(void* const* d_in, const int* in_sizes, int n_in,
                              void* d_out, int out_size) {
    const float* x     = (const float*)d_in[0];
    const float* n1g   = (const float*)d_in[1];
    const float* n1b   = (const float*)d_in[2];
    const float* qkvw  = (const float*)d_in[3];
    const float* qkvb  = (const float*)d_in[4];
    const float* projw = (const float*)d_in[5];
    const float* projb = (const float*)d_in[6];
    const float* rpb   = (const float*)d_in[7];
    const float* n2g   = (const float*)d_in[8];
    const float* n2b   = (const float*)d_in[9];
    const float* fc1w  = (const float*)d_in[10];
    const float* fc1b  = (const float*)d_in[11];
    const float* fc2w  = (const float*)d_in[12];
    const float* fc2b  = (const float*)d_in[13];
    float* out = (float*)d_out;

    static __half *p_xw16 = nullptr, *p_qkv16, *p_attn16, *p_ln216, *p_act16,
                  *p_qkvw16, *p_projw16, *p_fc1w16, *p_fc2w16;
    static float *p_h;
    if (!p_xw16) {
        cudaGetSymbolAddress((void**)&p_xw16,   g_xw16);
        cudaGetSymbolAddress((void**)&p_qkv16,  g_qkv16);
        cudaGetSymbolAddress((void**)&p_attn16, g_attn16);
        cudaGetSymbolAddress((void**)&p_h,      g_h);
        cudaGetSymbolAddress((void**)&p_ln216,  g_ln216);
        cudaGetSymbolAddress((void**)&p_act16,  g_act16);
        cudaGetSymbolAddress((void**)&p_qkvw16, g_qkvw16);
        cudaGetSymbolAddress((void**)&p_projw16,g_projw16);
        cudaGetSymbolAddress((void**)&p_fc1w16, g_fc1w16);
        cudaGetSymbolAddress((void**)&p_fc2w16, g_fc2w16);
        cudaFuncSetAttribute(gemm_wide, cudaFuncAttributeMaxDynamicSharedMemorySize, GSMEM);
    }

    // 0) weight conversion + bias/mask tables
    const int CV = 3 * Cc * Cc + Cc * Cc + HID * Cc + Cc * HID;
    cvt_all<<<(CV + 255) / 256, 256>>>(qkvw, projw, fc1w, fc2w);
    build_tab<<<24, 256>>>(rpb);

    // 1) LN1 + roll + window partition -> fp16
    ln1_shift_part<<<TOK / 8, 256>>>(x, n1g, n1b);
    // 2) QKV GEMM (wide; 8 perfect waves; Q prescaled by SCALE)
    gemm_wide<<<dim3(3, TOK / 128), 192, GSMEM>>>(p_xw16, p_qkvw16, qkvb, p_qkv16, 3 * Cc, Cc);
    // 3) window attention
    attn_k<<<dim3(NWTOT, NHd), 128>>>();
    // 4) proj GEMM + scatter + residual -> h (b256, 4 perfect waves)
    gemm_b256<2><<<dim3(3, TOK / 256), 256>>>(p_attn16, p_projw16, projb, x, p_h, Cc, Cc);
    // 5) LN2 -> fp16
    ln2_k<<<TOK / 8, 256>>>(n2g, n2b);
    // 6) FC1 + GELU -> fp16 (b256, 16 perfect waves)
    gemm_b256<1><<<dim3(HID / 64, TOK / 256), 256>>>(p_ln216, p_fc1w16, fc1b, nullptr, p_act16, HID, Cc);
    // 7) FC2 + residual -> out (b256, 16 perfect waves)
    gemm_b256<3><<<dim3(3, TOK / 256), 256>>>(p_act16, p_fc2w16, fc2b, p_h, out, Cc, HID);
}

// round 14
// speedup vs baseline: 1.1497x; 1.0665x over previous
#include <cuda_runtime.h>
#include <cuda_fp16.h>
#include <math.h>
#include <stddef.h>
#include <stdint.h>

#define Bb   32
#define Hh   56
#define Ww   56
#define Cc   192
#define WS   7
#define SS   3
#define NHd  6
#define Nn   49
#define HD   32
#define NWTOT 2048
#define TOK  100352
#define HID  768
#define SCALE 0.17677669529663687f  /* 32^-0.5 */

// ---------------- scratch (device globals; no allocations) ----------------
__device__ __half g_xw16  [(size_t)TOK * Cc];
__device__ __half g_qkv16 [(size_t)TOK * 3 * Cc];
__device__ __half g_attn16[(size_t)TOK * Cc];
__device__ float  g_h     [(size_t)TOK * Cc];
__device__ __half g_ln216 [(size_t)TOK * Cc];
__device__ __half g_act16 [(size_t)TOK * HID];
__device__ __half g_qkvw16[3 * Cc * Cc];
__device__ __half g_projw16[Cc * Cc];
__device__ __half g_fc1w16[HID * Cc];
__device__ __half g_fc2w16[Cc * HID];
__device__ float  g_tab   [24 * 64 * 64];     // (cls*6+nh) x 64 x 64 bias+mask

// ---------------- helpers ----------------
static __device__ __forceinline__ uint32_t smem_u32(const void* p) {
    uint32_t a;
    asm("{ .reg .u64 t; cvta.to.shared.u64 t, %1; cvt.u32.u64 %0, t; }" : "=r"(a) : "l"(p));
    return a;
}
static __device__ __forceinline__ void ldsm4(uint32_t& r0, uint32_t& r1, uint32_t& r2,
                                             uint32_t& r3, uint32_t addr) {
    asm volatile("ldmatrix.sync.aligned.m8n8.x4.shared.b16 {%0,%1,%2,%3}, [%4];"
                 : "=r"(r0), "=r"(r1), "=r"(r2), "=r"(r3) : "r"(addr));
}
static __device__ __forceinline__ void mma_f16(float* c, const uint32_t* a, const uint32_t* b) {
    asm volatile(
        "mma.sync.aligned.m16n8k16.row.col.f32.f16.f16.f32 "
        "{%0,%1,%2,%3}, {%4,%5,%6,%7}, {%8,%9}, {%0,%1,%2,%3};"
        : "+f"(c[0]), "+f"(c[1]), "+f"(c[2]), "+f"(c[3])
        : "r"(a[0]), "r"(a[1]), "r"(a[2]), "r"(a[3]), "r"(b[0]), "r"(b[1]));
}
static __device__ __forceinline__ void cpa16(uint32_t dst, const void* src) {
    asm volatile("cp.async.ca.shared.global [%0], [%1], 16;" :: "r"(dst), "l"(src));
}
static __device__ __forceinline__ uint32_t h2u(float a, float b) {
    __half2 h = __floats2half2_rn(a, b);
    return *(uint32_t*)&h;
}
#define DIV7(u) (((u) * 9363) >> 16)

static __device__ __forceinline__ float wsum(float v) {
    #pragma unroll
    for (int o = 16; o; o >>= 1) v += __shfl_xor_sync(0xffffffffu, v, o);
    return v;
}

// ---------------- fused weight conversion ----------------
__global__ void cvt_all(const float* __restrict__ qkvw, const float* __restrict__ projw,
                        const float* __restrict__ fc1w, const float* __restrict__ fc2w) {
    int i = blockIdx.x * 256 + threadIdx.x;
    const int S0 = 3 * Cc * Cc, S1 = Cc * Cc, S2 = HID * Cc, S3 = Cc * HID;
    if (i < S0) { g_qkvw16[i] = __float2half(qkvw[i]); return; }
    i -= S0;
    if (i < S1) { g_projw16[i] = __float2half(projw[i]); return; }
    i -= S1;
    if (i < S2) { g_fc1w16[i] = __float2half(fc1w[i]); return; }
    i -= S2;
    if (i < S3) { g_fc2w16[i] = __float2half(fc2w[i]); }
}

// ---------------- bias+mask tables: 4 window classes x 6 heads x 64x64 ----------------
__global__ void build_tab(const float* __restrict__ rpb) {
    int cls = blockIdx.x / NHd, nh = blockIdx.x - cls * NHd;
    int lastR = (cls >> 1) & 1, lastC = cls & 1;
    float* tp = g_tab + blockIdx.x * 4096;
    for (int idx = threadIdx.x; idx < 4096; idx += 256) {
        int rI = idx >> 6, m = idx & 63;
        float v;
        if (rI >= Nn) v = 0.0f;
        else if (m >= Nn) v = -1e30f;
        else {
            int r1 = DIV7(rI), c1 = rI - r1 * 7;
            int r2 = DIV7(m),  c2 = m  - r2 * 7;
            float bias = rpb[((r1 - r2 + 6) * 13 + (c1 - c2 + 6)) * NHd + nh];
            int rg1 = (lastR ? (r1 < 4 ? 1 : 2) : 0) * 3 + (lastC ? (c1 < 4 ? 1 : 2) : 0);
            int rg2 = (lastR ? (r2 < 4 ? 1 : 2) : 0) * 3 + (lastC ? (c2 < 4 ? 1 : 2) : 0);
            v = bias + ((rg1 == rg2) ? 0.0f : -100.0f);
        }
        tp[idx] = v;
    }
}

// ---------------- LN1 + roll(-3,-3) + window partition (warp per token) ----------------
__global__ void __launch_bounds__(256)
ln1_shift_part(const float* __restrict__ x, const float* __restrict__ g,
               const float* __restrict__ b) {
    int t = blockIdx.x * 8 + (threadIdx.x >> 5);
    int lane = threadIdx.x & 31;
    int wi = t / Nn, n = t - wi * Nn;
    int bi = wi >> 6, wl = wi & 63;
    int wr = wl >> 3, wc = wl & 7;
    int r = DIV7(n), c2 = n - r * 7;
    int hsrc = (wr * 7 + r + SS) % Hh;
    int wsrc = (wc * 7 + c2 + SS) % Ww;
    const float* row = x + ((size_t)bi * (Hh * Ww) + hsrc * Ww + wsrc) * Cc;
    float v[6];
    float s = 0.0f;
    #pragma unroll
    for (int j = 0; j < 6; j++) { v[j] = row[lane + 32 * j]; s += v[j]; }
    float mean = wsum(s) * (1.0f / Cc);
    float q = 0.0f;
    #pragma unroll
    for (int j = 0; j < 6; j++) { v[j] -= mean; q += v[j] * v[j]; }
    float inv = rsqrtf(wsum(q) * (1.0f / Cc) + 1e-5f);
    __half* o = g_xw16 + (size_t)t * Cc;
    #pragma unroll
    for (int j = 0; j < 6; j++) {
        int c = lane + 32 * j;
        o[c] = __float2half(v[j] * inv * g[c] + b[c]);
    }
}

// ---------------- LN2 (warp per token) ----------------
__global__ void __launch_bounds__(256)
ln2_k(const float* __restrict__ g, const float* __restrict__ b) {
    int t = blockIdx.x * 8 + (threadIdx.x >> 5);
    int lane = threadIdx.x & 31;
    const float* row = g_h + (size_t)t * Cc;
    float v[6];
    float s = 0.0f;
    #pragma unroll
    for (int j = 0; j < 6; j++) { v[j] = row[lane + 32 * j]; s += v[j]; }
    float mean = wsum(s) * (1.0f / Cc);
    float q = 0.0f;
    #pragma unroll
    for (int j = 0; j < 6; j++) { v[j] -= mean; q += v[j] * v[j]; }
    float inv = rsqrtf(wsum(q) * (1.0f / Cc) + 1e-5f);
    __half* o = g_ln216 + (size_t)t * Cc;
    #pragma unroll
    for (int j = 0; j < 6; j++) {
        int c = lane + 32 * j;
        o[c] = __float2half(v[j] * inv * g[c] + b[c]);
    }
}

// ---------------- wide fp16 TC GEMM: BM=128, BN=192, BK=32; 192 thr (qkv only) ----------------
#define A_STAGE 10240
#define B_STAGE 15360
#define GSMEM   (3 * (A_STAGE + B_STAGE))
__global__ void __launch_bounds__(192)
gemm_wide(const __half* __restrict__ A, const __half* __restrict__ Wt,
          const float* __restrict__ bias, __half* __restrict__ Cout, int Nc, int K) {
    extern __shared__ __align__(16) char smem[];
    const int tid  = threadIdx.x;
    const int wid  = tid >> 5, lane = tid & 31;
    const int gp   = lane >> 2, tg = lane & 3;
    const int m0   = blockIdx.y << 7;
    const int n0   = blockIdx.x * 192;
    const int wm   = (wid & 1) << 6;    // 0/64
    const int wn   = (wid >> 1) << 6;   // 0/64/128

    float acc[4][8][4];
    #pragma unroll
    for (int i = 0; i < 4; i++)
        #pragma unroll
        for (int j = 0; j < 8; j++)
            #pragma unroll
            for (int e = 0; e < 4; e++) acc[i][j][e] = 0.0f;

    const __half* Ap = A + (size_t)(m0 + tid) * K;         // valid for tid<128
    const __half* Wp = Wt + (size_t)(n0 + tid) * K;

    const uint32_t sA = smem_u32(smem);
    const uint32_t sB = sA + 3 * A_STAGE;
    const uint32_t aDst0 = sA + tid * 80;
    const uint32_t bDst0 = sB + tid * 80;

    const int aRow  = lane & 15;
    const int aCol8 = (lane >> 4) << 3;
    const int bRow  = ((lane & 16) >> 1) + (lane & 7);
    const int bCol8 = lane & 8;
    const uint32_t aOff = ((wm + aRow) * 40 + aCol8) << 1;
    const uint32_t bOff = ((wn + bRow) * 40 + bCol8) << 1;

    const int nc = K >> 5;

#define PREFETCH(ck, st) do {                                            \
        const __half* Ag_ = Ap + (ck) * 32;                              \
        const __half* Wg_ = Wp + (ck) * 32;                              \
        uint32_t aD_ = aDst0 + (st) * A_STAGE;                           \
        uint32_t bD_ = bDst0 + (st) * B_STAGE;                           \
        if (tid < 128) {                                                 \
            cpa16(aD_,      Ag_);      cpa16(aD_ + 16, Ag_ + 8);         \
            cpa16(aD_ + 32, Ag_ + 16); cpa16(aD_ + 48, Ag_ + 24);        \
        }                                                                \
        cpa16(bD_,      Wg_);      cpa16(bD_ + 16, Wg_ + 8);             \
        cpa16(bD_ + 32, Wg_ + 16); cpa16(bD_ + 48, Wg_ + 24);            \
        asm volatile("cp.async.commit_group;" ::: "memory");             \
    } while (0)

    PREFETCH(0, 0);
    PREFETCH(1, 1);

    for (int c = 0; c < nc; c++) {
        const int buf = c % 3;
        if (c + 1 < nc) asm volatile("cp.async.wait_group 1;" ::: "memory");
        else            asm volatile("cp.async.wait_group 0;" ::: "memory");
        __syncthreads();
        if (c + 2 < nc) PREFETCH(c + 2, (c + 2) % 3);

        const uint32_t aBase = sA + buf * A_STAGE + aOff;
        const uint32_t bBase = sB + buf * B_STAGE + bOff;
        #pragma unroll
        for (int kk = 0; kk < 2; kk++) {
            uint32_t af[4][4];
            #pragma unroll
            for (int i = 0; i < 4; i++)
                ldsm4(af[i][0], af[i][1], af[i][2], af[i][3],
                      aBase + ((i * 16 * 40 + kk * 16) << 1));
            uint32_t bf[16];
            #pragma unroll
            for (int j2 = 0; j2 < 4; j2++)
                ldsm4(bf[j2 * 4], bf[j2 * 4 + 1], bf[j2 * 4 + 2], bf[j2 * 4 + 3],
                      bBase + ((j2 * 16 * 40 + kk * 16) << 1));
            #pragma unroll
            for (int i = 0; i < 4; i++)
                #pragma unroll
                for (int j = 0; j < 8; j++)
                    mma_f16(acc[i][j], af[i], &bf[j * 2]);
        }
        __syncthreads();
    }
#undef PREFETCH

    #pragma unroll
    for (int i = 0; i < 4; i++) {
        #pragma unroll
        for (int half = 0; half < 2; half++) {
            const int row = m0 + wm + (i << 4) + gp + (half << 3);
            size_t rowoff = (size_t)row * Nc;
            #pragma unroll
            for (int j = 0; j < 8; j++) {
                const int ncol = n0 + wn + (j << 3) + (tg << 1);
                float v0 = acc[i][j][half * 2 + 0] + bias[ncol + 0];
                float v1 = acc[i][j][half * 2 + 1] + bias[ncol + 1];
                if (ncol < Cc) { v0 *= SCALE; v1 *= SCALE; }
                *(__half2*)(Cout + rowoff + ncol) = __floats2half2_rn(v0, v1);
            }
        }
    }
}

// ---------------- BM=256, BN=64, BK=32; 256 thr, 2-stage (proj, fc2) ----------------
// EPI: 2 = +bias, scatter window->token, +resid -> fp32 (proj)
//      3 = +bias, +resid -> fp32 (fc2)
template <int EPI>
__global__ void __launch_bounds__(256)
gemm_b256(const __half* __restrict__ A, const __half* __restrict__ Wt,
          const float* __restrict__ bias, const float* __restrict__ resid,
          void* __restrict__ Cout, int Nc, int K) {
    __shared__ __half As[2][256 * 40];
    __shared__ __half Bs[2][64 * 40];

    const int tid  = threadIdx.x;
    const int wid  = tid >> 5, lane = tid & 31;
    const int gp   = lane >> 2, tg = lane & 3;
    const int m0   = blockIdx.y << 8;
    const int n0   = blockIdx.x << 6;
    const int wm   = (wid & 3) << 6;    // 0/64/128/192
    const int wn   = (wid >> 2) << 5;   // 0/32

    float acc[4][4][4];
    #pragma unroll
    for (int i = 0; i < 4; i++)
        #pragma unroll
        for (int j = 0; j < 4; j++)
            #pragma unroll
            for (int e = 0; e < 4; e++) acc[i][j][e] = 0.0f;

    const __half* Ap = A + (size_t)(m0 + tid) * K;
    const int bRowL  = tid >> 2, bQ = tid & 3;
    const __half* Wp = Wt + (size_t)(n0 + bRowL) * K + bQ * 8;

    const uint32_t sA = smem_u32(As), sB = smem_u32(Bs);
    const uint32_t aDst0 = sA + tid * 80;
    const uint32_t bDst0 = sB + (bRowL * 40 + bQ * 8) * 2;

    const int aRow  = lane & 15;
    const int aCol8 = (lane >> 4) << 3;
    const int bRow  = ((lane & 16) >> 1) + (lane & 7);
    const int bCol8 = lane & 8;
    const uint32_t aOff = ((wm + aRow) * 40 + aCol8) << 1;
    const uint32_t bOff = ((wn + bRow) * 40 + bCol8) << 1;

    const int nc = K >> 5;

    #pragma unroll
    for (int s = 0; s < 4; s++) cpa16(aDst0 + s * 16, Ap + s * 8);
    cpa16(bDst0, Wp);
    asm volatile("cp.async.commit_group;" ::: "memory");

    for (int c = 0; c < nc; c++) {
        const int buf = c & 1;
        if (c + 1 < nc) {
            const int nb = (c + 1) & 1;
            const uint32_t aD = aDst0 + nb * (256 * 80);
            const uint32_t bD = bDst0 + nb * (64 * 80);
            const __half* Ag = Ap + (c + 1) * 32;
            const __half* Wg = Wp + (c + 1) * 32;
            #pragma unroll
            for (int s = 0; s < 4; s++) cpa16(aD + s * 16, Ag + s * 8);
            cpa16(bD, Wg);
            asm volatile("cp.async.commit_group;" ::: "memory");
            asm volatile("cp.async.wait_group 1;" ::: "memory");
        } else {
            asm volatile("cp.async.wait_group 0;" ::: "memory");
        }
        __syncthreads();

        const uint32_t aBase = sA + buf * (256 * 80) + aOff;
        const uint32_t bBase = sB + buf * (64 * 80) + bOff;
        #pragma unroll
        for (int kk = 0; kk < 2; kk++) {
            uint32_t af[4][4];
            #pragma unroll
            for (int i = 0; i < 4; i++)
                ldsm4(af[i][0], af[i][1], af[i][2], af[i][3],
                      aBase + ((i * 16 * 40 + kk * 16) << 1));
            uint32_t bf[4][2];
            ldsm4(bf[0][0], bf[0][1], bf[1][0], bf[1][1], bBase + ((kk * 16) << 1));
            ldsm4(bf[2][0], bf[2][1], bf[3][0], bf[3][1], bBase + ((16 * 40 + kk * 16) << 1));
            #pragma unroll
            for (int i = 0; i < 4; i++)
                #pragma unroll
                for (int j = 0; j < 4; j++)
                    mma_f16(acc[i][j], af[i], bf[j]);
        }
        __syncthreads();
    }

    #pragma unroll
    for (int i = 0; i < 4; i++) {
        #pragma unroll
        for (int half = 0; half < 2; half++) {
            const int row = m0 + wm + (i << 4) + gp + (half << 3);
            size_t rowoff;
            if (EPI == 2) {
                int wi2 = row / Nn, nn2 = row - wi2 * Nn;
                int bi = wi2 >> 6, wl = wi2 & 63;
                int wr = wl >> 3, wc = wl & 7;
                int rr = DIV7(nn2), cc = nn2 - rr * 7;
                int hd = (wr * 7 + rr + SS) % Hh;
                int wd = (wc * 7 + cc + SS) % Ww;
                rowoff = ((size_t)bi * (Hh * Ww) + hd * Ww + wd) * (size_t)Nc;
            } else {
                rowoff = (size_t)row * Nc;
            }
            #pragma unroll
            for (int j = 0; j < 4; j++) {
                const int ncol = n0 + wn + (j << 3) + (tg << 1);
                float v0 = acc[i][j][half * 2 + 0] + bias[ncol + 0] + resid[rowoff + ncol + 0];
                float v1 = acc[i][j][half * 2 + 1] + bias[ncol + 1] + resid[rowoff + ncol + 1];
                *(float2*)((float*)Cout + rowoff + ncol) = make_float2(v0, v1);
            }
        }
    }
}

// ---------------- fc1: K-resident-A GEMM. BM=256, full K=192 in smem, n-loop 12x64 ----------------
// A (g_ln216 tile) loaded ONCE; B double-buffered, prefetch distance 1. GELU epilogue -> fp16.
// smem: A 256x200 halfs (102400B) + B 2x64x200 (51200B) = 153600B -> 1 CTA/SM.
#define FC1_SMEM (256 * 400 + 2 * 64 * 400)
__global__ void __launch_bounds__(256)
gemm_fc1(const __half* __restrict__ A, const __half* __restrict__ Wt,
         const float* __restrict__ bias, __half* __restrict__ Cout) {
    extern __shared__ __align__(16) char smem[];
    const int tid = threadIdx.x;
    const int wid = tid >> 5, lane = tid & 31;
    const int gp  = lane >> 2, tg = lane & 3;
    const int m0  = blockIdx.x << 8;
    const int wm  = (wid & 3) << 6;    // 0/64/128/192
    const int wn  = (wid >> 2) << 5;   // 0/32

    const uint32_t sA = smem_u32(smem);
    const uint32_t sB = sA + 256 * 400;

    // ---- load A tile (256 rows x 192 halfs), one row per thread, pitch 200 halfs ----
    {
        const __half* src = A + (size_t)(m0 + tid) * Cc;
        uint32_t dst = sA + tid * 400;
        #pragma unroll
        for (int s = 0; s < 24; s++) cpa16(dst + s * 16, src + s * 8);
    }
    // ---- B chunk 0 (rows 0..63 of fc1w) ----
    const int bLRow = tid >> 2, bQ = tid & 3;
    {
        const __half* src = Wt + (size_t)bLRow * Cc + bQ * 48;
        uint32_t dst = sB + bLRow * 400 + bQ * 96;
        #pragma unroll
        for (int s = 0; s < 6; s++) cpa16(dst + s * 16, src + s * 8);
    }
    asm volatile("cp.async.commit_group;" ::: "memory");

    const int aRow  = lane & 15;
    const int aCol8 = (lane >> 4) << 3;
    const int bRow  = ((lane & 16) >> 1) + (lane & 7);
    const int bCol8 = lane & 8;
    const uint32_t aBase0 = sA + (((wm + aRow) * 200 + aCol8) << 1);
    const uint32_t bOff   = (((wn + bRow) * 200 + bCol8) << 1);

    for (int ncx = 0; ncx < 12; ncx++) {
        // prefetch next B chunk into the other buffer
        if (ncx + 1 < 12) {
            const __half* src = Wt + (size_t)((ncx + 1) * 64 + bLRow) * Cc + bQ * 48;
            uint32_t dst = sB + (((ncx + 1) & 1) ? 64 * 400 : 0) + bLRow * 400 + bQ * 96;
            #pragma unroll
            for (int s = 0; s < 6; s++) cpa16(dst + s * 16, src + s * 8);
            asm volatile("cp.async.commit_group;" ::: "memory");
            asm volatile("cp.async.wait_group 1;" ::: "memory");
        } else {
            asm volatile("cp.async.wait_group 0;" ::: "memory");
        }
        __syncthreads();

        float acc[4][4][4];
        #pragma unroll
        for (int i = 0; i < 4; i++)
            #pragma unroll
            for (int j = 0; j < 4; j++)
                #pragma unroll
                for (int e = 0; e < 4; e++) acc[i][j][e] = 0.0f;

        const uint32_t bB = sB + ((ncx & 1) ? 64 * 400 : 0) + bOff;
        #pragma unroll
        for (int kk = 0; kk < 12; kk++) {
            uint32_t af[4][4];
            #pragma unroll
            for (int i = 0; i < 4; i++)
                ldsm4(af[i][0], af[i][1], af[i][2], af[i][3],
                      aBase0 + ((i * 16 * 200 + kk * 16) << 1));
            uint32_t bf[4][2];
            ldsm4(bf[0][0], bf[0][1], bf[1][0], bf[1][1], bB + ((kk * 16) << 1));
            ldsm4(bf[2][0], bf[2][1], bf[3][0], bf[3][1], bB + ((16 * 200 + kk * 16) << 1));
            #pragma unroll
            for (int i = 0; i < 4; i++)
                #pragma unroll
                for (int j = 0; j < 4; j++)
                    mma_f16(acc[i][j], af[i], bf[j]);
        }

        // epilogue for this n-chunk: bias + GELU -> fp16
        #pragma unroll
        for (int i = 0; i < 4; i++) {
            #pragma unroll
            for (int half = 0; half < 2; half++) {
                const int row = m0 + wm + (i << 4) + gp + (half << 3);
                size_t rowoff = (size_t)row * HID;
                #pragma unroll
                for (int j = 0; j < 4; j++) {
                    const int ncol = ncx * 64 + wn + (j << 3) + (tg << 1);
                    float v0 = acc[i][j][half * 2 + 0] + bias[ncol + 0];
                    float v1 = acc[i][j][half * 2 + 1] + bias[ncol + 1];
                    v0 = 0.5f * v0 * (1.0f + erff(v0 * 0.70710678118654752f));
                    v1 = 0.5f * v1 * (1.0f + erff(v1 * 0.70710678118654752f));
                    *(__half2*)(Cout + rowoff + ncol) = __floats2half2_rn(v0, v1);
                }
            }
        }
        __syncthreads();   // protect B buffer before next-iteration prefetch overwrite
    }
}

// ---------------- tensor-core window attention: block = (window, head), 128 thr ----------------
__global__ void __launch_bounds__(128)
attn_k() {
    __shared__ __half Qs[64 * 40];
    __shared__ __half Ks[64 * 40];
    __shared__ __half Vt[32 * 72];

    const int wi = blockIdx.x;
    const int nh = blockIdx.y;
    const int tid = threadIdx.x;
    const int wid = tid >> 5, lane = tid & 31;
    const int gp = lane >> 2, tg = lane & 3;

    const int wl = wi & 63;
    const int cls = (((wl >> 3) == 7) ? 2 : 0) | (((wl & 7) == 7) ? 1 : 0);
    const float* tp = g_tab + (cls * NHd + nh) * 4096;

    for (int idx = tid; idx < 64 * 4; idx += 128) {
        int row = idx >> 2, seg = idx & 3;
        uint4 zq = make_uint4(0, 0, 0, 0), zk = zq;
        if (row < Nn) {
            const __half* base = g_qkv16 + (size_t)(wi * Nn + row) * (3 * Cc) + nh * HD + seg * 8;
            zq = *(const uint4*)(base);
            zk = *(const uint4*)(base + Cc);
        }
        *(uint4*)(Qs + row * 40 + seg * 8) = zq;
        *(uint4*)(Ks + row * 40 + seg * 8) = zk;
    }
    for (int idx = tid; idx < 64 * 16; idx += 128) {
        int row = idx >> 4, p = idx & 15;
        __half2 v = __float2half2_rn(0.0f);
        if (row < Nn)
            v = *(const __half2*)(g_qkv16 + (size_t)(wi * Nn + row) * (3 * Cc) + 2 * Cc + nh * HD + 2 * p);
        Vt[(2 * p) * 72 + row]     = __low2half(v);
        Vt[(2 * p + 1) * 72 + row] = __high2half(v);
    }

    const int rowL = wid * 16 + gp, rowH = rowL + 8;
    float st[8][4];
    #pragma unroll
    for (int j = 0; j < 8; j++) {
        float2 vL = *(const float2*)(tp + rowL * 64 + j * 8 + tg * 2);
        float2 vH = *(const float2*)(tp + rowH * 64 + j * 8 + tg * 2);
        st[j][0] = vL.x; st[j][1] = vL.y;
        st[j][2] = vH.x; st[j][3] = vH.y;
    }
    __syncthreads();

    const int aRow  = lane & 15;
    const int aCol8 = (lane >> 4) << 3;
    const int bRow  = ((lane & 16) >> 1) + (lane & 7);
    const int bCol8 = lane & 8;
    const uint32_t qBase = smem_u32(Qs) + (((wid * 16 + aRow) * 40 + aCol8) << 1);
    const uint32_t kBase = smem_u32(Ks) + ((bRow * 40 + bCol8) << 1);

    #pragma unroll
    for (int kk = 0; kk < 2; kk++) {
        uint32_t af[4];
        ldsm4(af[0], af[1], af[2], af[3], qBase + (kk * 16 << 1));
        #pragma unroll
        for (int j2 = 0; j2 < 4; j2++) {
            uint32_t bf[2][2];
            ldsm4(bf[0][0], bf[0][1], bf[1][0], bf[1][1],
                  kBase + ((j2 * 16 * 40 + kk * 16) << 1));
            mma_f16(st[2 * j2],     af, bf[0]);
            mma_f16(st[2 * j2 + 1], af, bf[1]);
        }
    }

    #pragma unroll
    for (int hrow = 0; hrow < 2; hrow++) {
        float mx = -1e30f;
        #pragma unroll
        for (int j = 0; j < 8; j++) {
            mx = fmaxf(mx, st[j][hrow * 2]);
            mx = fmaxf(mx, st[j][hrow * 2 + 1]);
        }
        mx = fmaxf(mx, __shfl_xor_sync(0xffffffffu, mx, 1));
        mx = fmaxf(mx, __shfl_xor_sync(0xffffffffu, mx, 2));
        float sm = 0.0f;
        #pragma unroll
        for (int j = 0; j < 8; j++) {
            #pragma unroll
            for (int e = 0; e < 2; e++) {
                float ev = __expf(st[j][hrow * 2 + e] - mx);
                st[j][hrow * 2 + e] = ev;
                sm += ev;
            }
        }
        sm += __shfl_xor_sync(0xffffffffu, sm, 1);
        sm += __shfl_xor_sync(0xffffffffu, sm, 2);
        float inv = 1.0f / sm;
        #pragma unroll
        for (int j = 0; j < 8; j++) {
            st[j][hrow * 2] *= inv;
            st[j][hrow * 2 + 1] *= inv;
        }
    }

    float o[4][4];
    #pragma unroll
    for (int jt = 0; jt < 4; jt++)
        #pragma unroll
        for (int e = 0; e < 4; e++) o[jt][e] = 0.0f;

    const uint32_t vBase = smem_u32(Vt) + ((bRow * 72 + bCol8) << 1);
    #pragma unroll
    for (int kk = 0; kk < 4; kk++) {
        uint32_t a[4];
        a[0] = h2u(st[2 * kk][0],     st[2 * kk][1]);
        a[1] = h2u(st[2 * kk][2],     st[2 * kk][3]);
        a[2] = h2u(st[2 * kk + 1][0], st[2 * kk + 1][1]);
        a[3] = h2u(st[2 * kk + 1][2], st[2 * kk + 1][3]);
        #pragma unroll
        for (int jj2 = 0; jj2 < 2; jj2++) {
            uint32_t bf[2][2];
            ldsm4(bf[0][0], bf[0][1], bf[1][0], bf[1][1],
                  vBase + ((jj2 * 16 * 72 + kk * 16) << 1));
            mma_f16(o[2 * jj2],     a, bf[0]);
            mma_f16(o[2 * jj2 + 1], a, bf[1]);
        }
    }

    __half* outp = g_attn16 + (size_t)wi * Nn * Cc + nh * HD;
    #pragma unroll
    for (int hrow = 0; hrow < 2; hrow++) {
        const int rI = hrow ? rowH : rowL;
        if (rI < Nn) {
            __half* rp = outp + (size_t)rI * Cc;
            #pragma unroll
            for (int jt = 0; jt < 4; jt++)
                *(__half2*)(rp + jt * 8 + tg * 2) =
                    __floats2half2_rn(o[jt][hrow * 2], o[jt][hrow * 2 + 1]);
        }
    }
}

// ---------------- host ----------------
extern "C" void kernel_launch(void* const* d_in, const int* in_sizes, int n_in,
                              void* d_out, int out_size) {
    const float* x     = (const float*)d_in[0];
    const float* n1g   = (const float*)d_in[1];
    const float* n1b   = (const float*)d_in[2];
    const float* qkvw  = (const float*)d_in[3];
    const float* qkvb  = (const float*)d_in[4];
    const float* projw = (const float*)d_in[5];
    const float* projb = (const float*)d_in[6];
    const float* rpb   = (const float*)d_in[7];
    const float* n2g   = (const float*)d_in[8];
    const float* n2b   = (const float*)d_in[9];
    const float* fc1w  = (const float*)d_in[10];
    const float* fc1b  = (const float*)d_in[11];
    const float* fc2w  = (const float*)d_in[12];
    const float* fc2b  = (const float*)d_in[13];
    float* out = (float*)d_out;

    static __half *p_xw16 = nullptr, *p_qkv16, *p_attn16, *p_ln216, *p_act16,
                  *p_qkvw16, *p_projw16, *p_fc1w16, *p_fc2w16;
    static float *p_h;
    if (!p_xw16) {
        cudaGetSymbolAddress((void**)&p_xw16,   g_xw16);
        cudaGetSymbolAddress((void**)&p_qkv16,  g_qkv16);
        cudaGetSymbolAddress((void**)&p_attn16, g_attn16);
        cudaGetSymbolAddress((void**)&p_h,      g_h);
        cudaGetSymbolAddress((void**)&p_ln216,  g_ln216);
        cudaGetSymbolAddress((void**)&p_act16,  g_act16);
        cudaGetSymbolAddress((void**)&p_qkvw16, g_qkvw16);
        cudaGetSymbolAddress((void**)&p_projw16,g_projw16);
        cudaGetSymbolAddress((void**)&p_fc1w16, g_fc1w16);
        cudaGetSymbolAddress((void**)&p_fc2w16, g_fc2w16);
        cudaFuncSetAttribute(gemm_wide, cudaFuncAttributeMaxDynamicSharedMemorySize, GSMEM);
        cudaFuncSetAttribute(gemm_fc1,  cudaFuncAttributeMaxDynamicSharedMemorySize, FC1_SMEM);
    }

    // 0) weight conversion + bias/mask tables
    const int CV = 3 * Cc * Cc + Cc * Cc + HID * Cc + Cc * HID;
    cvt_all<<<(CV + 255) / 256, 256>>>(qkvw, projw, fc1w, fc2w);
    build_tab<<<24, 256>>>(rpb);

    // 1) LN1 + roll + window partition -> fp16
    ln1_shift_part<<<TOK / 8, 256>>>(x, n1g, n1b);
    // 2) QKV GEMM (wide; 8 perfect waves; Q prescaled by SCALE)
    gemm_wide<<<dim3(3, TOK / 128), 192, GSMEM>>>(p_xw16, p_qkvw16, qkvb, p_qkv16, 3 * Cc, Cc);
    // 3) window attention
    attn_k<<<dim3(NWTOT, NHd), 128>>>();
    // 4) proj GEMM + scatter + residual -> h (b256)
    gemm_b256<2><<<dim3(3, TOK / 256), 256>>>(p_attn16, p_projw16, projb, x, p_h, Cc, Cc);
    // 5) LN2 -> fp16
    ln2_k<<<TOK / 8, 256>>>(n2g, n2b);
    // 6) FC1 + GELU -> fp16 (K-resident-A, A loaded once per tile)
    gemm_fc1<<<TOK / 256, 256, FC1_SMEM>>>(p_ln216, p_fc1w16, fc1b, p_act16);
    // 7) FC2 + residual -> out (b256)
    gemm_b256<3><<<dim3(3, TOK / 256), 256>>>(p_act16, p_fc2w16, fc2b, p_h, out, Cc, HID);
}

// round 15
// speedup vs baseline: 1.1958x; 1.0400x over previous
#include <cuda_runtime.h>
#include <cuda_fp16.h>
#include <math.h>
#include <stddef.h>
#include <stdint.h>

#define Bb   32
#define Hh   56
#define Ww   56
#define Cc   192
#define WS   7
#define SS   3
#define NHd  6
#define Nn   49
#define HD   32
#define NWTOT 2048
#define TOK  100352
#define HID  768
#define SCALE 0.17677669529663687f  /* 32^-0.5 */

// ---------------- scratch (device globals; no allocations) ----------------
__device__ __half g_xw16  [(size_t)TOK * Cc];
__device__ __half g_qkv16 [(size_t)TOK * 3 * Cc];
__device__ __half g_attn16[(size_t)TOK * Cc];
__device__ float  g_h     [(size_t)TOK * Cc];
__device__ __half g_ln216 [(size_t)TOK * Cc];
__device__ __half g_act16 [(size_t)TOK * HID];
__device__ __half g_qkvw16[3 * Cc * Cc];
__device__ __half g_projw16[Cc * Cc];
__device__ __half g_fc1w16[HID * Cc];
__device__ __half g_fc2w16[Cc * HID];
__device__ float  g_tab   [24 * 64 * 64];     // (cls*6+nh) x 64 x 64 bias+mask

// ---------------- helpers ----------------
static __device__ __forceinline__ uint32_t smem_u32(const void* p) {
    uint32_t a;
    asm("{ .reg .u64 t; cvta.to.shared.u64 t, %1; cvt.u32.u64 %0, t; }" : "=r"(a) : "l"(p));
    return a;
}
static __device__ __forceinline__ void ldsm4(uint32_t& r0, uint32_t& r1, uint32_t& r2,
                                             uint32_t& r3, uint32_t addr) {
    asm volatile("ldmatrix.sync.aligned.m8n8.x4.shared.b16 {%0,%1,%2,%3}, [%4];"
                 : "=r"(r0), "=r"(r1), "=r"(r2), "=r"(r3) : "r"(addr));
}
static __device__ __forceinline__ void mma_f16(float* c, const uint32_t* a, const uint32_t* b) {
    asm volatile(
        "mma.sync.aligned.m16n8k16.row.col.f32.f16.f16.f32 "
        "{%0,%1,%2,%3}, {%4,%5,%6,%7}, {%8,%9}, {%0,%1,%2,%3};"
        : "+f"(c[0]), "+f"(c[1]), "+f"(c[2]), "+f"(c[3])
        : "r"(a[0]), "r"(a[1]), "r"(a[2]), "r"(a[3]), "r"(b[0]), "r"(b[1]));
}
static __device__ __forceinline__ void cpa16(uint32_t dst, const void* src) {
    asm volatile("cp.async.ca.shared.global [%0], [%1], 16;" :: "r"(dst), "l"(src));
}
static __device__ __forceinline__ uint32_t h2u(float a, float b) {
    __half2 h = __floats2half2_rn(a, b);
    return *(uint32_t*)&h;
}
#define DIV7(u) (((u) * 9363) >> 16)

static __device__ __forceinline__ float wsum(float v) {
    #pragma unroll
    for (int o = 16; o; o >>= 1) v += __shfl_xor_sync(0xffffffffu, v, o);
    return v;
}

// ---------------- fused weight conversion + bias/mask tables ----------------
__global__ void cvt_all(const float* __restrict__ qkvw, const float* __restrict__ projw,
                        const float* __restrict__ fc1w, const float* __restrict__ fc2w,
                        const float* __restrict__ rpb) {
    int i = blockIdx.x * 256 + threadIdx.x;
    const int S0 = 3 * Cc * Cc, S1 = Cc * Cc, S2 = HID * Cc, S3 = Cc * HID;
    if (i < S0) { g_qkvw16[i] = __float2half(qkvw[i]); return; }
    i -= S0;
    if (i < S1) { g_projw16[i] = __float2half(projw[i]); return; }
    i -= S1;
    if (i < S2) { g_fc1w16[i] = __float2half(fc1w[i]); return; }
    i -= S2;
    if (i < S3) { g_fc2w16[i] = __float2half(fc2w[i]); return; }
    i -= S3;
    if (i < 24 * 4096) {
        int tb = i >> 12, idx = i & 4095;
        int cls = tb / NHd, nh = tb - cls * NHd;
        int lastR = (cls >> 1) & 1, lastC = cls & 1;
        int rI = idx >> 6, m = idx & 63;
        float v;
        if (rI >= Nn) v = 0.0f;
        else if (m >= Nn) v = -1e30f;
        else {
            int r1 = DIV7(rI), c1 = rI - r1 * 7;
            int r2 = DIV7(m),  c2 = m  - r2 * 7;
            float bias = rpb[((r1 - r2 + 6) * 13 + (c1 - c2 + 6)) * NHd + nh];
            int rg1 = (lastR ? (r1 < 4 ? 1 : 2) : 0) * 3 + (lastC ? (c1 < 4 ? 1 : 2) : 0);
            int rg2 = (lastR ? (r2 < 4 ? 1 : 2) : 0) * 3 + (lastC ? (c2 < 4 ? 1 : 2) : 0);
            v = bias + ((rg1 == rg2) ? 0.0f : -100.0f);
        }
        g_tab[(size_t)tb * 4096 + idx] = v;
    }
}

// ---------------- LN1 + roll(-3,-3) + window partition (warp per token) ----------------
__global__ void __launch_bounds__(256)
ln1_shift_part(const float* __restrict__ x, const float* __restrict__ g,
               const float* __restrict__ b) {
    int t = blockIdx.x * 8 + (threadIdx.x >> 5);
    int lane = threadIdx.x & 31;
    int wi = t / Nn, n = t - wi * Nn;
    int bi = wi >> 6, wl = wi & 63;
    int wr = wl >> 3, wc = wl & 7;
    int r = DIV7(n), c2 = n - r * 7;
    int hsrc = (wr * 7 + r + SS) % Hh;
    int wsrc = (wc * 7 + c2 + SS) % Ww;
    const float* row = x + ((size_t)bi * (Hh * Ww) + hsrc * Ww + wsrc) * Cc;
    float v[6];
    float s = 0.0f;
    #pragma unroll
    for (int j = 0; j < 6; j++) { v[j] = row[lane + 32 * j]; s += v[j]; }
    float mean = wsum(s) * (1.0f / Cc);
    float q = 0.0f;
    #pragma unroll
    for (int j = 0; j < 6; j++) { v[j] -= mean; q += v[j] * v[j]; }
    float inv = rsqrtf(wsum(q) * (1.0f / Cc) + 1e-5f);
    __half* o = g_xw16 + (size_t)t * Cc;
    #pragma unroll
    for (int j = 0; j < 6; j++) {
        int c = lane + 32 * j;
        o[c] = __float2half(v[j] * inv * g[c] + b[c]);
    }
}

// ---------------- LN2 (warp per token) ----------------
__global__ void __launch_bounds__(256)
ln2_k(const float* __restrict__ g, const float* __restrict__ b) {
    int t = blockIdx.x * 8 + (threadIdx.x >> 5);
    int lane = threadIdx.x & 31;
    const float* row = g_h + (size_t)t * Cc;
    float v[6];
    float s = 0.0f;
    #pragma unroll
    for (int j = 0; j < 6; j++) { v[j] = row[lane + 32 * j]; s += v[j]; }
    float mean = wsum(s) * (1.0f / Cc);
    float q = 0.0f;
    #pragma unroll
    for (int j = 0; j < 6; j++) { v[j] -= mean; q += v[j] * v[j]; }
    float inv = rsqrtf(wsum(q) * (1.0f / Cc) + 1e-5f);
    __half* o = g_ln216 + (size_t)t * Cc;
    #pragma unroll
    for (int j = 0; j < 6; j++) {
        int c = lane + 32 * j;
        o[c] = __float2half(v[j] * inv * g[c] + b[c]);
    }
}

// ---------------- K-resident-A GEMM (K=192): BM=256, n-loop NCH x 64 ----------------
// A tile loaded ONCE (256x192, pitch 200); B double-buffered (64x192 chunks).
// 256 thr, 8 warps (4m x 2n), warp tile 64x32.
// EPI: 0 = +bias, cols<192 scaled by SCALE -> fp16 (qkv)
//      1 = +bias, GELU -> fp16 (fc1)
#define KR_SMEM (256 * 400 + 2 * 64 * 400)
template <int NCH, int EPI>
__global__ void __launch_bounds__(256)
gemm_kr(const __half* __restrict__ A, const __half* __restrict__ Wt,
        const float* __restrict__ bias, __half* __restrict__ Cout) {
    extern __shared__ __align__(16) char smem[];
    const int Nc  = NCH * 64;
    const int tid = threadIdx.x;
    const int wid = tid >> 5, lane = tid & 31;
    const int gp  = lane >> 2, tg = lane & 3;
    const int m0  = blockIdx.x << 8;
    const int wm  = (wid & 3) << 6;    // 0/64/128/192
    const int wn  = (wid >> 2) << 5;   // 0/32

    const uint32_t sA = smem_u32(smem);
    const uint32_t sB = sA + 256 * 400;

    // ---- load A tile (256 rows x 192 halfs), one row per thread, pitch 200 halfs ----
    {
        const __half* src = A + (size_t)(m0 + tid) * Cc;
        uint32_t dst = sA + tid * 400;
        #pragma unroll
        for (int s = 0; s < 24; s++) cpa16(dst + s * 16, src + s * 8);
    }
    // ---- B chunk 0 ----
    const int bLRow = tid >> 2, bQ = tid & 3;
    {
        const __half* src = Wt + (size_t)bLRow * Cc + bQ * 48;
        uint32_t dst = sB + bLRow * 400 + bQ * 96;
        #pragma unroll
        for (int s = 0; s < 6; s++) cpa16(dst + s * 16, src + s * 8);
    }
    asm volatile("cp.async.commit_group;" ::: "memory");

    const int aRow  = lane & 15;
    const int aCol8 = (lane >> 4) << 3;
    const int bRow  = ((lane & 16) >> 1) + (lane & 7);
    const int bCol8 = lane & 8;
    const uint32_t aBase0 = sA + (((wm + aRow) * 200 + aCol8) << 1);
    const uint32_t bOff   = (((wn + bRow) * 200 + bCol8) << 1);

    for (int ncx = 0; ncx < NCH; ncx++) {
        if (ncx + 1 < NCH) {
            const __half* src = Wt + (size_t)((ncx + 1) * 64 + bLRow) * Cc + bQ * 48;
            uint32_t dst = sB + (((ncx + 1) & 1) ? 64 * 400 : 0) + bLRow * 400 + bQ * 96;
            #pragma unroll
            for (int s = 0; s < 6; s++) cpa16(dst + s * 16, src + s * 8);
            asm volatile("cp.async.commit_group;" ::: "memory");
            asm volatile("cp.async.wait_group 1;" ::: "memory");
        } else {
            asm volatile("cp.async.wait_group 0;" ::: "memory");
        }
        __syncthreads();

        float acc[4][4][4];
        #pragma unroll
        for (int i = 0; i < 4; i++)
            #pragma unroll
            for (int j = 0; j < 4; j++)
                #pragma unroll
                for (int e = 0; e < 4; e++) acc[i][j][e] = 0.0f;

        const uint32_t bB = sB + ((ncx & 1) ? 64 * 400 : 0) + bOff;
        #pragma unroll
        for (int kk = 0; kk < 12; kk++) {
            uint32_t af[4][4];
            #pragma unroll
            for (int i = 0; i < 4; i++)
                ldsm4(af[i][0], af[i][1], af[i][2], af[i][3],
                      aBase0 + ((i * 16 * 200 + kk * 16) << 1));
            uint32_t bf[4][2];
            ldsm4(bf[0][0], bf[0][1], bf[1][0], bf[1][1], bB + ((kk * 16) << 1));
            ldsm4(bf[2][0], bf[2][1], bf[3][0], bf[3][1], bB + ((16 * 200 + kk * 16) << 1));
            #pragma unroll
            for (int i = 0; i < 4; i++)
                #pragma unroll
                for (int j = 0; j < 4; j++)
                    mma_f16(acc[i][j], af[i], bf[j]);
        }

        // epilogue for this n-chunk
        #pragma unroll
        for (int i = 0; i < 4; i++) {
            #pragma unroll
            for (int half = 0; half < 2; half++) {
                const int row = m0 + wm + (i << 4) + gp + (half << 3);
                size_t rowoff = (size_t)row * Nc;
                #pragma unroll
                for (int j = 0; j < 4; j++) {
                    const int ncol = ncx * 64 + wn + (j << 3) + (tg << 1);
                    float v0 = acc[i][j][half * 2 + 0] + bias[ncol + 0];
                    float v1 = acc[i][j][half * 2 + 1] + bias[ncol + 1];
                    if (EPI == 0 && ncol < Cc) { v0 *= SCALE; v1 *= SCALE; }
                    if (EPI == 1) {
                        v0 = 0.5f * v0 * (1.0f + erff(v0 * 0.70710678118654752f));
                        v1 = 0.5f * v1 * (1.0f + erff(v1 * 0.70710678118654752f));
                    }
                    *(__half2*)(Cout + rowoff + ncol) = __floats2half2_rn(v0, v1);
                }
            }
        }
        __syncthreads();   // protect B buffer before next prefetch overwrite
    }
}

// ---------------- BM=256, BN=64, BK=32; 256 thr, 2-stage (proj, fc2) ----------------
// EPI: 2 = +bias, scatter window->token, +resid -> fp32 (proj)
//      3 = +bias, +resid -> fp32 (fc2)
template <int EPI>
__global__ void __launch_bounds__(256)
gemm_b256(const __half* __restrict__ A, const __half* __restrict__ Wt,
          const float* __restrict__ bias, const float* __restrict__ resid,
          void* __restrict__ Cout, int Nc, int K) {
    __shared__ __half As[2][256 * 40];
    __shared__ __half Bs[2][64 * 40];

    const int tid  = threadIdx.x;
    const int wid  = tid >> 5, lane = tid & 31;
    const int gp   = lane >> 2, tg = lane & 3;
    const int m0   = blockIdx.y << 8;
    const int n0   = blockIdx.x << 6;
    const int wm   = (wid & 3) << 6;    // 0/64/128/192
    const int wn   = (wid >> 2) << 5;   // 0/32

    float acc[4][4][4];
    #pragma unroll
    for (int i = 0; i < 4; i++)
        #pragma unroll
        for (int j = 0; j < 4; j++)
            #pragma unroll
            for (int e = 0; e < 4; e++) acc[i][j][e] = 0.0f;

    const __half* Ap = A + (size_t)(m0 + tid) * K;
    const int bRowL  = tid >> 2, bQ = tid & 3;
    const __half* Wp = Wt + (size_t)(n0 + bRowL) * K + bQ * 8;

    const uint32_t sA = smem_u32(As), sB = smem_u32(Bs);
    const uint32_t aDst0 = sA + tid * 80;
    const uint32_t bDst0 = sB + (bRowL * 40 + bQ * 8) * 2;

    const int aRow  = lane & 15;
    const int aCol8 = (lane >> 4) << 3;
    const int bRow  = ((lane & 16) >> 1) + (lane & 7);
    const int bCol8 = lane & 8;
    const uint32_t aOff = ((wm + aRow) * 40 + aCol8) << 1;
    const uint32_t bOff = ((wn + bRow) * 40 + bCol8) << 1;

    const int nc = K >> 5;

    #pragma unroll
    for (int s = 0; s < 4; s++) cpa16(aDst0 + s * 16, Ap + s * 8);
    cpa16(bDst0, Wp);
    asm volatile("cp.async.commit_group;" ::: "memory");

    for (int c = 0; c < nc; c++) {
        const int buf = c & 1;
        if (c + 1 < nc) {
            const int nb = (c + 1) & 1;
            const uint32_t aD = aDst0 + nb * (256 * 80);
            const uint32_t bD = bDst0 + nb * (64 * 80);
            const __half* Ag = Ap + (c + 1) * 32;
            const __half* Wg = Wp + (c + 1) * 32;
            #pragma unroll
            for (int s = 0; s < 4; s++) cpa16(aD + s * 16, Ag + s * 8);
            cpa16(bD, Wg);
            asm volatile("cp.async.commit_group;" ::: "memory");
            asm volatile("cp.async.wait_group 1;" ::: "memory");
        } else {
            asm volatile("cp.async.wait_group 0;" ::: "memory");
        }
        __syncthreads();

        const uint32_t aBase = sA + buf * (256 * 80) + aOff;
        const uint32_t bBase = sB + buf * (64 * 80) + bOff;
        #pragma unroll
        for (int kk = 0; kk < 2; kk++) {
            uint32_t af[4][4];
            #pragma unroll
            for (int i = 0; i < 4; i++)
                ldsm4(af[i][0], af[i][1], af[i][2], af[i][3],
                      aBase + ((i * 16 * 40 + kk * 16) << 1));
            uint32_t bf[4][2];
            ldsm4(bf[0][0], bf[0][1], bf[1][0], bf[1][1], bBase + ((kk * 16) << 1));
            ldsm4(bf[2][0], bf[2][1], bf[3][0], bf[3][1], bBase + ((16 * 40 + kk * 16) << 1));
            #pragma unroll
            for (int i = 0; i < 4; i++)
                #pragma unroll
                for (int j = 0; j < 4; j++)
                    mma_f16(acc[i][j], af[i], bf[j]);
        }
        __syncthreads();
    }

    #pragma unroll
    for (int i = 0; i < 4; i++) {
        #pragma unroll
        for (int half = 0; half < 2; half++) {
            const int row = m0 + wm + (i << 4) + gp + (half << 3);
            size_t rowoff;
            if (EPI == 2) {
                int wi2 = row / Nn, nn2 = row - wi2 * Nn;
                int bi = wi2 >> 6, wl = wi2 & 63;
                int wr = wl >> 3, wc = wl & 7;
                int rr = DIV7(nn2), cc = nn2 - rr * 7;
                int hd = (wr * 7 + rr + SS) % Hh;
                int wd = (wc * 7 + cc + SS) % Ww;
                rowoff = ((size_t)bi * (Hh * Ww) + hd * Ww + wd) * (size_t)Nc;
            } else {
                rowoff = (size_t)row * Nc;
            }
            #pragma unroll
            for (int j = 0; j < 4; j++) {
                const int ncol = n0 + wn + (j << 3) + (tg << 1);
                float v0 = acc[i][j][half * 2 + 0] + bias[ncol + 0] + resid[rowoff + ncol + 0];
                float v1 = acc[i][j][half * 2 + 1] + bias[ncol + 1] + resid[rowoff + ncol + 1];
                *(float2*)((float*)Cout + rowoff + ncol) = make_float2(v0, v1);
            }
        }
    }
}

// ---------------- tensor-core window attention: block = (window, head), 128 thr ----------------
__global__ void __launch_bounds__(128)
attn_k() {
    __shared__ __half Qs[64 * 40];
    __shared__ __half Ks[64 * 40];
    __shared__ __half Vt[32 * 72];

    const int wi = blockIdx.x;
    const int nh = blockIdx.y;
    const int tid = threadIdx.x;
    const int wid = tid >> 5, lane = tid & 31;
    const int gp = lane >> 2, tg = lane & 3;

    const int wl = wi & 63;
    const int cls = (((wl >> 3) == 7) ? 2 : 0) | (((wl & 7) == 7) ? 1 : 0);
    const float* tp = g_tab + (cls * NHd + nh) * 4096;

    for (int idx = tid; idx < 64 * 4; idx += 128) {
        int row = idx >> 2, seg = idx & 3;
        uint4 zq = make_uint4(0, 0, 0, 0), zk = zq;
        if (row < Nn) {
            const __half* base = g_qkv16 + (size_t)(wi * Nn + row) * (3 * Cc) + nh * HD + seg * 8;
            zq = *(const uint4*)(base);
            zk = *(const uint4*)(base + Cc);
        }
        *(uint4*)(Qs + row * 40 + seg * 8) = zq;
        *(uint4*)(Ks + row * 40 + seg * 8) = zk;
    }
    for (int idx = tid; idx < 64 * 16; idx += 128) {
        int row = idx >> 4, p = idx & 15;
        __half2 v = __float2half2_rn(0.0f);
        if (row < Nn)
            v = *(const __half2*)(g_qkv16 + (size_t)(wi * Nn + row) * (3 * Cc) + 2 * Cc + nh * HD + 2 * p);
        Vt[(2 * p) * 72 + row]     = __low2half(v);
        Vt[(2 * p + 1) * 72 + row] = __high2half(v);
    }

    const int rowL = wid * 16 + gp, rowH = rowL + 8;
    float st[8][4];
    #pragma unroll
    for (int j = 0; j < 8; j++) {
        float2 vL = *(const float2*)(tp + rowL * 64 + j * 8 + tg * 2);
        float2 vH = *(const float2*)(tp + rowH * 64 + j * 8 + tg * 2);
        st[j][0] = vL.x; st[j][1] = vL.y;
        st[j][2] = vH.x; st[j][3] = vH.y;
    }
    __syncthreads();

    const int aRow  = lane & 15;
    const int aCol8 = (lane >> 4) << 3;
    const int bRow  = ((lane & 16) >> 1) + (lane & 7);
    const int bCol8 = lane & 8;
    const uint32_t qBase = smem_u32(Qs) + (((wid * 16 + aRow) * 40 + aCol8) << 1);
    const uint32_t kBase = smem_u32(Ks) + ((bRow * 40 + bCol8) << 1);

    #pragma unroll
    for (int kk = 0; kk < 2; kk++) {
        uint32_t af[4];
        ldsm4(af[0], af[1], af[2], af[3], qBase + (kk * 16 << 1));
        #pragma unroll
        for (int j2 = 0; j2 < 4; j2++) {
            uint32_t bf[2][2];
            ldsm4(bf[0][0], bf[0][1], bf[1][0], bf[1][1],
                  kBase + ((j2 * 16 * 40 + kk * 16) << 1));
            mma_f16(st[2 * j2],     af, bf[0]);
            mma_f16(st[2 * j2 + 1], af, bf[1]);
        }
    }

    #pragma unroll
    for (int hrow = 0; hrow < 2; hrow++) {
        float mx = -1e30f;
        #pragma unroll
        for (int j = 0; j < 8; j++) {
            mx = fmaxf(mx, st[j][hrow * 2]);
            mx = fmaxf(mx, st[j][hrow * 2 + 1]);
        }
        mx = fmaxf(mx, __shfl_xor_sync(0xffffffffu, mx, 1));
        mx = fmaxf(mx, __shfl_xor_sync(0xffffffffu, mx, 2));
        float sm = 0.0f;
        #pragma unroll
        for (int j = 0; j < 8; j++) {
            #pragma unroll
            for (int e = 0; e < 2; e++) {
                float ev = __expf(st[j][hrow * 2 + e] - mx);
                st[j][hrow * 2 + e] = ev;
                sm += ev;
            }
        }
        sm += __shfl_xor_sync(0xffffffffu, sm, 1);
        sm += __shfl_xor_sync(0xffffffffu, sm, 2);
        float inv = 1.0f / sm;
        #pragma unroll
        for (int j = 0; j < 8; j++) {
            st[j][hrow * 2] *= inv;
            st[j][hrow * 2 + 1] *= inv;
        }
    }

    float o[4][4];
    #pragma unroll
    for (int jt = 0; jt < 4; jt++)
        #pragma unroll
        for (int e = 0; e < 4; e++) o[jt][e] = 0.0f;

    const uint32_t vBase = smem_u32(Vt) + ((bRow * 72 + bCol8) << 1);
    #pragma unroll
    for (int kk = 0; kk < 4; kk++) {
        uint32_t a[4];
        a[0] = h2u(st[2 * kk][0],     st[2 * kk][1]);
        a[1] = h2u(st[2 * kk][2],     st[2 * kk][3]);
        a[2] = h2u(st[2 * kk + 1][0], st[2 * kk + 1][1]);
        a[3] = h2u(st[2 * kk + 1][2], st[2 * kk + 1][3]);
        #pragma unroll
        for (int jj2 = 0; jj2 < 2; jj2++) {
            uint32_t bf[2][2];
            ldsm4(bf[0][0], bf[0][1], bf[1][0], bf[1][1],
                  vBase + ((jj2 * 16 * 72 + kk * 16) << 1));
            mma_f16(o[2 * jj2],     a, bf[0]);
            mma_f16(o[2 * jj2 + 1], a, bf[1]);
        }
    }

    __half* outp = g_attn16 + (size_t)wi * Nn * Cc + nh * HD;
    #pragma unroll
    for (int hrow = 0; hrow < 2; hrow++) {
        const int rI = hrow ? rowH : rowL;
        if (rI < Nn) {
            __half* rp = outp + (size_t)rI * Cc;
            #pragma unroll
            for (int jt = 0; jt < 4; jt++)
                *(__half2*)(rp + jt * 8 + tg * 2) =
                    __floats2half2_rn(o[jt][hrow * 2], o[jt][hrow * 2 + 1]);
        }
    }
}

// ---------------- host ----------------
extern "C" void kernel_launch(void* const* d_in, const int* in_sizes, int n_in,
                              void* d_out, int out_size) {
    const float* x     = (const float*)d_in[0];
    const float* n1g   = (const float*)d_in[1];
    const float* n1b   = (const float*)d_in[2];
    const float* qkvw  = (const float*)d_in[3];
    const float* qkvb  = (const float*)d_in[4];
    const float* projw = (const float*)d_in[5];
    const float* projb = (const float*)d_in[6];
    const float* rpb   = (const float*)d_in[7];
    const float* n2g   = (const float*)d_in[8];
    const float* n2b   = (const float*)d_in[9];
    const float* fc1w  = (const float*)d_in[10];
    const float* fc1b  = (const float*)d_in[11];
    const float* fc2w  = (const float*)d_in[12];
    const float* fc2b  = (const float*)d_in[13];
    float* out = (float*)d_out;

    static __half *p_xw16 = nullptr, *p_qkv16, *p_attn16, *p_ln216, *p_act16,
                  *p_qkvw16, *p_projw16, *p_fc1w16, *p_fc2w16;
    static float *p_h;
    if (!p_xw16) {
        cudaGetSymbolAddress((void**)&p_xw16,   g_xw16);
        cudaGetSymbolAddress((void**)&p_qkv16,  g_qkv16);
        cudaGetSymbolAddress((void**)&p_attn16, g_attn16);
        cudaGetSymbolAddress((void**)&p_h,      g_h);
        cudaGetSymbolAddress((void**)&p_ln216,  g_ln216);
        cudaGetSymbolAddress((void**)&p_act16,  g_act16);
        cudaGetSymbolAddress((void**)&p_qkvw16, g_qkvw16);
        cudaGetSymbolAddress((void**)&p_projw16,g_projw16);
        cudaGetSymbolAddress((void**)&p_fc1w16, g_fc1w16);
        cudaGetSymbolAddress((void**)&p_fc2w16, g_fc2w16);
        cudaFuncSetAttribute((const void*)gemm_kr<9, 0>,  cudaFuncAttributeMaxDynamicSharedMemorySize, KR_SMEM);
        cudaFuncSetAttribute((const void*)gemm_kr<12, 1>, cudaFuncAttributeMaxDynamicSharedMemorySize, KR_SMEM);
    }

    // 0) weight conversion + bias/mask tables (one launch)
    const int CV = 3 * Cc * Cc + Cc * Cc + HID * Cc + Cc * HID + 24 * 4096;
    cvt_all<<<(CV + 255) / 256, 256>>>(qkvw, projw, fc1w, fc2w, rpb);

    // 1) LN1 + roll + window partition -> fp16
    ln1_shift_part<<<TOK / 8, 256>>>(x, n1g, n1b);
    // 2) QKV GEMM (K-resident-A; Q prescaled by SCALE)
    gemm_kr<9, 0><<<TOK / 256, 256, KR_SMEM>>>(p_xw16, p_qkvw16, qkvb, p_qkv16);
    // 3) window attention
    attn_k<<<dim3(NWTOT, NHd), 128>>>();
    // 4) proj GEMM + scatter + residual -> h (b256)
    gemm_b256<2><<<dim3(3, TOK / 256), 256>>>(p_attn16, p_projw16, projb, x, p_h, Cc, Cc);
    // 5) LN2 -> fp16
    ln2_k<<<TOK / 8, 256>>>(n2g, n2b);
    // 6) FC1 + GELU -> fp16 (K-resident-A)
    gemm_kr<12, 1><<<TOK / 256, 256, KR_SMEM>>>(p_ln216, p_fc1w16, fc1b, p_act16);
    // 7) FC2 + residual -> out (b256)
    gemm_b256<3><<<dim3(3, TOK / 256), 256>>>(p_act16, p_fc2w16, fc2b, p_h, out, Cc, HID);
}